// round 7
// baseline (speedup 1.0000x reference)
#include <cuda_runtime.h>
#include <cuda_bf16.h>
#include <math.h>

// Problem constants
#define NN    4096          // graph nodes
#define TT    48            // timesteps
#define HH    64            // hidden
#define INW   2             // input width
#define PP    12            // output width
#define G4    256           // 4*H
#define RT0   32            // rows per block, cell0
#define RT1   16            // rows per block, cell1 (2x work/row -> balanced blocks)
#define NB0   (NN / RT0)    // 128 blocks for cell0
#define NB1   (NN / RT1)    // 256 blocks for cell1

#define NNZ_MAX (1 << 19)

// ---------------- device scratch -------------------------------------------------
__device__ int   g_rowptr[NN + 1];
__device__ int   g_rowcnt[NN];
__device__ int   g_col[NNZ_MAX];
__device__ float g_val[NNZ_MAX];
__device__ float g_dinv[NN];
__device__ float g_xT[NN * 96];   // x transposed: [node][t*2+c]
__device__ float g_AX[NN * 96];   // A @ x, same layout
__device__ float g_h0[2][NN * HH];
__device__ float g_c0[2][NN * HH];
__device__ float g_h1[2][NN * HH];
__device__ float g_c1[2][NN * HH];

__device__ __forceinline__ float sigm(float x) { return 1.0f / (1.0f + expf(-x)); }

// ---------------- preprocessing -------------------------------------------------
__global__ void degree_kernel(const float* __restrict__ adj) {
    const int i = blockIdx.x;
    const int tid = threadIdx.x;
    const float* row = adj + (size_t)i * NN;
    float d = 0.0f;
    int cnt = 0;
    for (int j = tid; j < NN; j += blockDim.x) {
        const float a = __ldg(&row[j]);
        d += a;
        cnt += (a != 0.0f && j != i) ? 1 : 0;
    }
    __shared__ float sd[128];
    __shared__ int   sc[128];
    sd[tid] = d; sc[tid] = cnt;
    __syncthreads();
    for (int off = 64; off > 0; off >>= 1) {
        if (tid < off) { sd[tid] += sd[tid + off]; sc[tid] += sc[tid + off]; }
        __syncthreads();
    }
    if (tid == 0) {
        const float dd = sd[0] + 1.0f;
        g_dinv[i]   = 1.0f / sqrtf(dd);
        g_rowcnt[i] = sc[0] + 1;
    }
}

__global__ void scan_kernel() {
    __shared__ int s[1024];
    const int tid = threadIdx.x;
    int c[4];
    int sum = 0;
#pragma unroll
    for (int u = 0; u < 4; ++u) { c[u] = g_rowcnt[tid * 4 + u]; sum += c[u]; }
    s[tid] = sum;
    __syncthreads();
    for (int off = 1; off < 1024; off <<= 1) {
        const int v = (tid >= off) ? s[tid - off] : 0;
        __syncthreads();
        s[tid] += v;
        __syncthreads();
    }
    int excl = s[tid] - sum;
#pragma unroll
    for (int u = 0; u < 4; ++u) { g_rowptr[tid * 4 + u] = excl; excl += c[u]; }
    if (tid == 1023) g_rowptr[NN] = s[1023];
}

__global__ void fill_kernel(const float* __restrict__ adj) {
    const int w = (blockIdx.x * blockDim.x + threadIdx.x) >> 5;
    const int lane = threadIdx.x & 31;
    if (w >= NN) return;
    const int i = w;
    const float* row = adj + (size_t)i * NN;
    const float di = g_dinv[i];
    int base = g_rowptr[i];
    for (int j0 = 0; j0 < NN; j0 += 32) {
        const int j = j0 + lane;
        const float a = __ldg(&row[j]);
        const bool pred = (a != 0.0f) || (j == i);
        const unsigned mask = __ballot_sync(0xffffffffu, pred);
        if (pred) {
            const int idx = base + __popc(mask & ((1u << lane) - 1u));
            if (idx < NNZ_MAX) {
                g_col[idx] = j;
                const float v = a + ((j == i) ? 1.0f : 0.0f);
                g_val[idx] = di * g_dinv[j] * v;
            }
        }
        base += __popc(mask);
    }
}

__global__ void xT_kernel(const float* __restrict__ x) {
    const int idx = blockIdx.x * blockDim.x + threadIdx.x;
    if (idx >= NN * 96) return;
    const int n = idx / 96;
    const int k = idx % 96;
    const int t = k >> 1;
    const int c = k & 1;
    g_xT[idx] = __ldg(&x[t * (NN * INW) + n * INW + c]);
}

__global__ void ax_kernel() {
    const int i = blockIdx.x;
    const int k = threadIdx.x;  // 0..95
    const int p0 = g_rowptr[i], p1 = g_rowptr[i + 1];
    float acc = 0.0f;
    for (int p = p0; p < p1; ++p)
        acc = fmaf(g_val[p], g_xT[g_col[p] * 96 + k], acc);
    g_AX[i * 96 + k] = acc;
}

__global__ void zero_kernel() {
    const int idx = blockIdx.x * blockDim.x + threadIdx.x;
    if (idx < NN * HH) {
        g_h0[0][idx] = 0.0f; g_c0[0][idx] = 0.0f;
        g_h1[0][idx] = 0.0f; g_c1[0][idx] = 0.0f;
    }
}

// ---------------- cell bodies ----------------------------------------------------
// Shared buffer: 4224 floats (16.9 KB), 16B aligned for float4 shared reads.
//   cell0: sAh[32][64] @0, sH[32][64] @2048, sXA[32][2] @4096, sXI[32][2] @4160
//   cell1: sAi[16][64] @0, sAh[16][64] @1024, sI[16][64] @2048, sH[16][64] @3072
#define SBUF_F 4224

__device__ __forceinline__ void cell0_body(
    float* __restrict__ sbuf, int row0, int t,
    const float* __restrict__ h_in, const float* __restrict__ c_in,
    float* __restrict__ h_out, float* __restrict__ c_out,
    const float* __restrict__ Wgi, const float* __restrict__ Wgh,
    const float* __restrict__ Wli, const float* __restrict__ Wlh,
    const float* __restrict__ bgi, const float* __restrict__ bgh,
    const float* __restrict__ bli, const float* __restrict__ blh)
{
    const int tid = threadIdx.x;
    const int m   = tid & 63;
    const int rg  = tid >> 6;

    float* sAh = sbuf;           // [32][64]
    float* sH  = sbuf + 2048;    // [32][64]
    float* sXA = sbuf + 4096;    // [32][2]
    float* sXI = sbuf + 4160;    // [32][2]

    for (int r = rg; r < RT0; r += 4) {
        const int i = row0 + r;
        sH[r * 64 + m] = __ldg(&h_in[i * HH + m]);
        const int p0 = g_rowptr[i];
        const int p1 = g_rowptr[i + 1];
        float a0 = 0.0f, a1 = 0.0f;
        int p = p0;
#pragma unroll 2
        for (; p + 2 <= p1; p += 2) {
            a0 = fmaf(g_val[p],     __ldg(&h_in[g_col[p]     * HH + m]), a0);
            a1 = fmaf(g_val[p + 1], __ldg(&h_in[g_col[p + 1] * HH + m]), a1);
        }
        if (p < p1)
            a0 = fmaf(g_val[p], __ldg(&h_in[g_col[p] * HH + m]), a0);
        sAh[r * 64 + m] = a0 + a1;
        if (m < 2) {
            sXA[r * 2 + m] = g_AX[i * 96 + 2 * t + m];
            sXI[r * 2 + m] = g_xT[i * 96 + 2 * t + m];
        }
    }
    __syncthreads();

    const int kk = m;
    const int rbase = rg * 8;

    float ai[8], af[8], ao[8], ag[8];
    {
        const float b0 = __ldg(&bgi[kk      ]) + __ldg(&bgh[kk      ]) + __ldg(&bli[kk      ]) + __ldg(&blh[kk      ]);
        const float b1 = __ldg(&bgi[kk +  64]) + __ldg(&bgh[kk +  64]) + __ldg(&bli[kk +  64]) + __ldg(&blh[kk +  64]);
        const float b2 = __ldg(&bgi[kk + 128]) + __ldg(&bgh[kk + 128]) + __ldg(&bli[kk + 128]) + __ldg(&blh[kk + 128]);
        const float b3 = __ldg(&bgi[kk + 192]) + __ldg(&bgh[kk + 192]) + __ldg(&bli[kk + 192]) + __ldg(&blh[kk + 192]);
#pragma unroll
        for (int r = 0; r < 8; ++r) { ai[r] = b0; af[r] = b1; ao[r] = b2; ag[r] = b3; }
    }

#define C0_ACC(W, S)                                                         \
    for (int mm = 0; mm < HH; mm += 4) {                                     \
        float w0[4], w1[4], w2[4], w3[4];                                    \
        _Pragma("unroll")                                                    \
        for (int u = 0; u < 4; ++u) {                                        \
            w0[u] = __ldg(&W[(mm + u) * G4 + kk      ]);                     \
            w1[u] = __ldg(&W[(mm + u) * G4 + kk +  64]);                     \
            w2[u] = __ldg(&W[(mm + u) * G4 + kk + 128]);                     \
            w3[u] = __ldg(&W[(mm + u) * G4 + kk + 192]);                     \
        }                                                                    \
        _Pragma("unroll")                                                    \
        for (int r = 0; r < 8; ++r) {                                        \
            const float4 v = *(const float4*)&S[(rbase + r) * 64 + mm];      \
            ai[r] = fmaf(v.x, w0[0], ai[r]); af[r] = fmaf(v.x, w1[0], af[r]);\
            ao[r] = fmaf(v.x, w2[0], ao[r]); ag[r] = fmaf(v.x, w3[0], ag[r]);\
            ai[r] = fmaf(v.y, w0[1], ai[r]); af[r] = fmaf(v.y, w1[1], af[r]);\
            ao[r] = fmaf(v.y, w2[1], ao[r]); ag[r] = fmaf(v.y, w3[1], ag[r]);\
            ai[r] = fmaf(v.z, w0[2], ai[r]); af[r] = fmaf(v.z, w1[2], af[r]);\
            ao[r] = fmaf(v.z, w2[2], ao[r]); ag[r] = fmaf(v.z, w3[2], ag[r]);\
            ai[r] = fmaf(v.w, w0[3], ai[r]); af[r] = fmaf(v.w, w1[3], af[r]);\
            ao[r] = fmaf(v.w, w2[3], ao[r]); ag[r] = fmaf(v.w, w3[3], ag[r]);\
        }                                                                    \
    }

    C0_ACC(Wgh, sAh)
    C0_ACC(Wlh, sH)
#undef C0_ACC

#pragma unroll
    for (int mm = 0; mm < INW; ++mm) {
        const float w0 = __ldg(&Wgi[mm * G4 + kk      ]);
        const float w1 = __ldg(&Wgi[mm * G4 + kk +  64]);
        const float w2 = __ldg(&Wgi[mm * G4 + kk + 128]);
        const float w3 = __ldg(&Wgi[mm * G4 + kk + 192]);
        const float u0 = __ldg(&Wli[mm * G4 + kk      ]);
        const float u1 = __ldg(&Wli[mm * G4 + kk +  64]);
        const float u2 = __ldg(&Wli[mm * G4 + kk + 128]);
        const float u3 = __ldg(&Wli[mm * G4 + kk + 192]);
#pragma unroll
        for (int r = 0; r < 8; ++r) {
            const float va = sXA[(rbase + r) * 2 + mm];
            const float vi = sXI[(rbase + r) * 2 + mm];
            ai[r] = fmaf(va, w0, ai[r]); af[r] = fmaf(va, w1, af[r]);
            ao[r] = fmaf(va, w2, ao[r]); ag[r] = fmaf(va, w3, ag[r]);
            ai[r] = fmaf(vi, u0, ai[r]); af[r] = fmaf(vi, u1, af[r]);
            ao[r] = fmaf(vi, u2, ao[r]); ag[r] = fmaf(vi, u3, ag[r]);
        }
    }

#pragma unroll
    for (int r = 0; r < 8; ++r) {
        const int i = row0 + rbase + r;
        const float cold = __ldg(&c_in[i * HH + kk]);
        const float igt = sigm(ai[r]);
        const float fgt = sigm(af[r]);
        const float ogt = sigm(ao[r]);
        const float ggt = tanhf(ag[r]);
        const float cn = fgt * cold + igt * ggt;
        c_out[i * HH + kk] = cn;
        h_out[i * HH + kk] = ogt * tanhf(cn);
    }
}

__device__ __forceinline__ void cell1_body(
    float* __restrict__ sbuf, int row0,
    const float* __restrict__ inp,  const float* __restrict__ h_in,
    const float* __restrict__ c_in,
    float* __restrict__ h_out, float* __restrict__ c_out,
    const float* __restrict__ Wgi, const float* __restrict__ Wgh,
    const float* __restrict__ Wli, const float* __restrict__ Wlh,
    const float* __restrict__ bgi, const float* __restrict__ bgh,
    const float* __restrict__ bli, const float* __restrict__ blh)
{
    const int tid = threadIdx.x;
    const int m   = tid & 63;
    const int rg  = tid >> 6;

    float* sAi = sbuf;           // [16][64]
    float* sAh = sbuf + 1024;
    float* sI  = sbuf + 2048;
    float* sH  = sbuf + 3072;

    for (int r = rg; r < RT1; r += 4) {
        const int i = row0 + r;
        sI[r * 64 + m] = __ldg(&inp [i * HH + m]);
        sH[r * 64 + m] = __ldg(&h_in[i * HH + m]);
        const int p0 = g_rowptr[i];
        const int p1 = g_rowptr[i + 1];
        float a0 = 0.0f, a1 = 0.0f, a2 = 0.0f, a3 = 0.0f;
        int p = p0;
#pragma unroll 2
        for (; p + 2 <= p1; p += 2) {
            const int   c0 = g_col[p];
            const int   c1 = g_col[p + 1];
            const float v0 = g_val[p];
            const float v1 = g_val[p + 1];
            a0 = fmaf(v0, __ldg(&inp [c0 * HH + m]), a0);
            a1 = fmaf(v0, __ldg(&h_in[c0 * HH + m]), a1);
            a2 = fmaf(v1, __ldg(&inp [c1 * HH + m]), a2);
            a3 = fmaf(v1, __ldg(&h_in[c1 * HH + m]), a3);
        }
        if (p < p1) {
            const int   c = g_col[p];
            const float v = g_val[p];
            a0 = fmaf(v, __ldg(&inp [c * HH + m]), a0);
            a1 = fmaf(v, __ldg(&h_in[c * HH + m]), a1);
        }
        sAi[r * 64 + m] = a0 + a2;
        sAh[r * 64 + m] = a1 + a3;
    }
    __syncthreads();

    const int kk = m;
    const int rbase = rg * 4;

    float ai[4], af[4], ao[4], ag[4];
    {
        const float b0 = __ldg(&bgi[kk      ]) + __ldg(&bgh[kk      ]) + __ldg(&bli[kk      ]) + __ldg(&blh[kk      ]);
        const float b1 = __ldg(&bgi[kk +  64]) + __ldg(&bgh[kk +  64]) + __ldg(&bli[kk +  64]) + __ldg(&blh[kk +  64]);
        const float b2 = __ldg(&bgi[kk + 128]) + __ldg(&bgh[kk + 128]) + __ldg(&bli[kk + 128]) + __ldg(&blh[kk + 128]);
        const float b3 = __ldg(&bgi[kk + 192]) + __ldg(&bgh[kk + 192]) + __ldg(&bli[kk + 192]) + __ldg(&blh[kk + 192]);
#pragma unroll
        for (int r = 0; r < 4; ++r) { ai[r] = b0; af[r] = b1; ao[r] = b2; ag[r] = b3; }
    }

#define C1_ACC(W, S)                                                         \
    for (int mm = 0; mm < HH; mm += 4) {                                     \
        float w0[4], w1[4], w2[4], w3[4];                                    \
        _Pragma("unroll")                                                    \
        for (int u = 0; u < 4; ++u) {                                        \
            w0[u] = __ldg(&W[(mm + u) * G4 + kk      ]);                     \
            w1[u] = __ldg(&W[(mm + u) * G4 + kk +  64]);                     \
            w2[u] = __ldg(&W[(mm + u) * G4 + kk + 128]);                     \
            w3[u] = __ldg(&W[(mm + u) * G4 + kk + 192]);                     \
        }                                                                    \
        _Pragma("unroll")                                                    \
        for (int r = 0; r < 4; ++r) {                                        \
            const float4 v = *(const float4*)&S[(rbase + r) * 64 + mm];      \
            ai[r] = fmaf(v.x, w0[0], ai[r]); af[r] = fmaf(v.x, w1[0], af[r]);\
            ao[r] = fmaf(v.x, w2[0], ao[r]); ag[r] = fmaf(v.x, w3[0], ag[r]);\
            ai[r] = fmaf(v.y, w0[1], ai[r]); af[r] = fmaf(v.y, w1[1], af[r]);\
            ao[r] = fmaf(v.y, w2[1], ao[r]); ag[r] = fmaf(v.y, w3[1], ag[r]);\
            ai[r] = fmaf(v.z, w0[2], ai[r]); af[r] = fmaf(v.z, w1[2], af[r]);\
            ao[r] = fmaf(v.z, w2[2], ao[r]); ag[r] = fmaf(v.z, w3[2], ag[r]);\
            ai[r] = fmaf(v.w, w0[3], ai[r]); af[r] = fmaf(v.w, w1[3], af[r]);\
            ao[r] = fmaf(v.w, w2[3], ao[r]); ag[r] = fmaf(v.w, w3[3], ag[r]);\
        }                                                                    \
    }

    C1_ACC(Wgi, sAi)
    C1_ACC(Wgh, sAh)
    C1_ACC(Wli, sI)
    C1_ACC(Wlh, sH)
#undef C1_ACC

#pragma unroll
    for (int r = 0; r < 4; ++r) {
        const int i = row0 + rbase + r;
        const float cold = __ldg(&c_in[i * HH + kk]);
        const float igt = sigm(ai[r]);
        const float fgt = sigm(af[r]);
        const float ogt = sigm(ao[r]);
        const float ggt = tanhf(ag[r]);
        const float cn = fgt * cold + igt * ggt;
        c_out[i * HH + kk] = cn;
        h_out[i * HH + kk] = ogt * tanhf(cn);
    }
}

// ---------------- kernels --------------------------------------------------------

// Standalone cell0 (first step only)
__global__ void __launch_bounds__(256, 2) cell0_kernel(
    int t, int rd,
    const float* __restrict__ Wgi, const float* __restrict__ Wgh,
    const float* __restrict__ Wli, const float* __restrict__ Wlh,
    const float* __restrict__ bgi, const float* __restrict__ bgh,
    const float* __restrict__ bli, const float* __restrict__ blh)
{
    __shared__ __align__(16) float sbuf[SBUF_F];
    cell0_body(sbuf, blockIdx.x * RT0, t,
               g_h0[rd], g_c0[rd], g_h0[rd ^ 1], g_c0[rd ^ 1],
               Wgi, Wgh, Wli, Wlh, bgi, bgh, bli, blh);
}

// Standalone cell1 (last step only)
__global__ void __launch_bounds__(256, 2) cell1_kernel(
    int rd,
    const float* __restrict__ Wgi, const float* __restrict__ Wgh,
    const float* __restrict__ Wli, const float* __restrict__ Wlh,
    const float* __restrict__ bgi, const float* __restrict__ bgh,
    const float* __restrict__ bli, const float* __restrict__ blh)
{
    __shared__ __align__(16) float sbuf[SBUF_F];
    cell1_body(sbuf, blockIdx.x * RT1,
               g_h0[rd ^ 1], g_h1[rd], g_c1[rd], g_h1[rd ^ 1], g_c1[rd ^ 1],
               Wgi, Wgh, Wli, Wlh, bgi, bgh, bli, blh);
}

// Fused: cell1(tnext-1) runs concurrently with cell0(tnext).
// Both read h0 written at step tnext-1 (buffer rd0); cell0 writes h0[rd0^1],
// cell1 writes h1[rd1^1]. No buffer is both read and written across roles.
__global__ void __launch_bounds__(256, 2) step_kernel(
    int tnext,
    const float* __restrict__ Wgi0, const float* __restrict__ Wgh0,
    const float* __restrict__ Wli0, const float* __restrict__ Wlh0,
    const float* __restrict__ bgi0, const float* __restrict__ bgh0,
    const float* __restrict__ bli0, const float* __restrict__ blh0,
    const float* __restrict__ Wgi1, const float* __restrict__ Wgh1,
    const float* __restrict__ Wli1, const float* __restrict__ Wlh1,
    const float* __restrict__ bgi1, const float* __restrict__ bgh1,
    const float* __restrict__ bli1, const float* __restrict__ blh1)
{
    __shared__ __align__(16) float sbuf[SBUF_F];
    const int rd0 = tnext & 1;         // cell0 parity at step tnext
    const int rd1 = rd0 ^ 1;           // cell1 parity at step tnext-1
    if (blockIdx.x < NB0) {
        cell0_body(sbuf, blockIdx.x * RT0, tnext,
                   g_h0[rd0], g_c0[rd0], g_h0[rd0 ^ 1], g_c0[rd0 ^ 1],
                   Wgi0, Wgh0, Wli0, Wlh0, bgi0, bgh0, bli0, blh0);
    } else {
        cell1_body(sbuf, (blockIdx.x - NB0) * RT1,
                   g_h0[rd0],                  // inp = h0(tnext-1)
                   g_h1[rd1], g_c1[rd1], g_h1[rd1 ^ 1], g_c1[rd1 ^ 1],
                   Wgi1, Wgh1, Wli1, Wlh1, bgi1, bgh1, bli1, blh1);
    }
}

// Final projection: out[i,p] = h1[i,:] @ outW[:,p] + outb[p]
__global__ void out_kernel(const float* __restrict__ outW,
                           const float* __restrict__ outb,
                           float* __restrict__ out)
{
    const int idx = blockIdx.x * blockDim.x + threadIdx.x;
    if (idx >= NN * PP) return;
    const int i = idx / PP;
    const int p = idx % PP;
    const float* h = &g_h1[0][i * HH];   // parity 0 after 48 steps
    float acc = __ldg(&outb[p]);
#pragma unroll
    for (int mm = 0; mm < HH; ++mm)
        acc = fmaf(h[mm], __ldg(&outW[mm * PP + p]), acc);
    out[idx] = acc;
}

// ---------------- launch --------------------------------------------------------
extern "C" void kernel_launch(void* const* d_in, const int* in_sizes, int n_in,
                              void* d_out, int out_size) {
    const float* x     = (const float*)d_in[0];
    const float* adj   = (const float*)d_in[1];
    const float* gcWi0 = (const float*)d_in[2];  const float* gcbi0 = (const float*)d_in[3];
    const float* gcWh0 = (const float*)d_in[4];  const float* gcbh0 = (const float*)d_in[5];
    const float* liWi0 = (const float*)d_in[6];  const float* libi0 = (const float*)d_in[7];
    const float* liWh0 = (const float*)d_in[8];  const float* libh0 = (const float*)d_in[9];
    const float* gcWi1 = (const float*)d_in[10]; const float* gcbi1 = (const float*)d_in[11];
    const float* gcWh1 = (const float*)d_in[12]; const float* gcbh1 = (const float*)d_in[13];
    const float* liWi1 = (const float*)d_in[14]; const float* libi1 = (const float*)d_in[15];
    const float* liWh1 = (const float*)d_in[16]; const float* libh1 = (const float*)d_in[17];
    const float* outW  = (const float*)d_in[18]; const float* outb  = (const float*)d_in[19];
    float* out = (float*)d_out;

    // Preprocessing (captured in the graph; deterministic)
    degree_kernel<<<NN, 128>>>(adj);
    scan_kernel<<<1, 1024>>>();
    fill_kernel<<<(NN * 32 + 255) / 256, 256>>>(adj);
    xT_kernel<<<(NN * 96 + 255) / 256, 256>>>(x);
    ax_kernel<<<NN, 96>>>();
    zero_kernel<<<(NN * HH + 255) / 256, 256>>>();

    // Step 0: cell0 alone (reads zeroed h0[0], writes h0[1])
    cell0_kernel<<<NB0, 256>>>(0, 0,
        gcWi0, gcWh0, liWi0, liWh0, gcbi0, gcbh0, libi0, libh0);

    // Steps: fused cell1(t-1) || cell0(t) for t = 1..47
    for (int tnext = 1; tnext < TT; ++tnext) {
        step_kernel<<<NB0 + NB1, 256>>>(tnext,
            gcWi0, gcWh0, liWi0, liWh0, gcbi0, gcbh0, libi0, libh0,
            gcWi1, gcWh1, liWi1, liWh1, gcbi1, gcbh1, libi1, libh1);
    }

    // Last: cell1 for step 47 (rd = 47 & 1 = 1)
    cell1_kernel<<<NB1, 256>>>(1,
        gcWi1, gcWh1, liWi1, liWh1, gcbi1, gcbh1, libi1, libh1);

    out_kernel<<<(NN * PP + 255) / 256, 256>>>(outW, outb, out);
}

// round 9
// speedup vs baseline: 1.3928x; 1.3928x over previous
#include <cuda_runtime.h>
#include <cuda_bf16.h>
#include <math.h>

// Problem constants
#define NN    4096          // graph nodes
#define TT    48            // timesteps
#define HH    64            // hidden
#define INW   2             // input width
#define PP    12            // output width
#define G4    256           // 4*H
#define RT0   32            // rows per block, cell0
#define RT1   16            // rows per block, cell1 (2x work/row -> balanced blocks)
#define NB0   (NN / RT0)    // 128 blocks for cell0
#define NB1   (NN / RT1)    // 256 blocks for cell1
#define CAP0  2048          // staged nnz cap, cell0 (expected ~1344/block)
#define CAP1  1024          // staged nnz cap, cell1 (expected ~672/block)

#define NNZ_MAX (1 << 19)

// ---------------- device scratch -------------------------------------------------
__device__ int   g_rowptr[NN + 1];
__device__ int   g_rowcnt[NN];
__device__ int   g_col[NNZ_MAX];
__device__ float g_val[NNZ_MAX];
__device__ float g_dinv[NN];
__device__ float g_xT[NN * 96];   // x transposed: [node][t*2+c]
__device__ float g_AX[NN * 96];   // A @ x, same layout
__device__ float g_h0[2][NN * HH];
__device__ float g_c0[2][NN * HH];
__device__ float g_h1[2][NN * HH];
__device__ float g_c1[2][NN * HH];

__device__ __forceinline__ float sigm(float x) { return 1.0f / (1.0f + expf(-x)); }

// ---------------- preprocessing -------------------------------------------------
__global__ void degree_kernel(const float* __restrict__ adj) {
    const int i = blockIdx.x;
    const int tid = threadIdx.x;
    const float* row = adj + (size_t)i * NN;
    float d = 0.0f;
    int cnt = 0;
    for (int j = tid; j < NN; j += blockDim.x) {
        const float a = __ldg(&row[j]);
        d += a;
        cnt += (a != 0.0f && j != i) ? 1 : 0;
    }
    __shared__ float sd[128];
    __shared__ int   sc[128];
    sd[tid] = d; sc[tid] = cnt;
    __syncthreads();
    for (int off = 64; off > 0; off >>= 1) {
        if (tid < off) { sd[tid] += sd[tid + off]; sc[tid] += sc[tid + off]; }
        __syncthreads();
    }
    if (tid == 0) {
        const float dd = sd[0] + 1.0f;
        g_dinv[i]   = 1.0f / sqrtf(dd);
        g_rowcnt[i] = sc[0] + 1;
    }
}

__global__ void scan_kernel() {
    __shared__ int s[1024];
    const int tid = threadIdx.x;
    int c[4];
    int sum = 0;
#pragma unroll
    for (int u = 0; u < 4; ++u) { c[u] = g_rowcnt[tid * 4 + u]; sum += c[u]; }
    s[tid] = sum;
    __syncthreads();
    for (int off = 1; off < 1024; off <<= 1) {
        const int v = (tid >= off) ? s[tid - off] : 0;
        __syncthreads();
        s[tid] += v;
        __syncthreads();
    }
    int excl = s[tid] - sum;
#pragma unroll
    for (int u = 0; u < 4; ++u) { g_rowptr[tid * 4 + u] = excl; excl += c[u]; }
    if (tid == 1023) g_rowptr[NN] = s[1023];
}

__global__ void fill_kernel(const float* __restrict__ adj) {
    const int w = (blockIdx.x * blockDim.x + threadIdx.x) >> 5;
    const int lane = threadIdx.x & 31;
    if (w >= NN) return;
    const int i = w;
    const float* row = adj + (size_t)i * NN;
    const float di = g_dinv[i];
    int base = g_rowptr[i];
    for (int j0 = 0; j0 < NN; j0 += 32) {
        const int j = j0 + lane;
        const float a = __ldg(&row[j]);
        const bool pred = (a != 0.0f) || (j == i);
        const unsigned mask = __ballot_sync(0xffffffffu, pred);
        if (pred) {
            const int idx = base + __popc(mask & ((1u << lane) - 1u));
            if (idx < NNZ_MAX) {
                g_col[idx] = j;
                const float v = a + ((j == i) ? 1.0f : 0.0f);
                g_val[idx] = di * g_dinv[j] * v;
            }
        }
        base += __popc(mask);
    }
}

__global__ void xT_kernel(const float* __restrict__ x) {
    const int idx = blockIdx.x * blockDim.x + threadIdx.x;
    if (idx >= NN * 96) return;
    const int n = idx / 96;
    const int k = idx % 96;
    const int t = k >> 1;
    const int c = k & 1;
    g_xT[idx] = __ldg(&x[t * (NN * INW) + n * INW + c]);
}

__global__ void ax_kernel() {
    const int i = blockIdx.x;
    const int k = threadIdx.x;  // 0..95
    const int p0 = g_rowptr[i], p1 = g_rowptr[i + 1];
    float acc = 0.0f;
    for (int p = p0; p < p1; ++p)
        acc = fmaf(g_val[p], g_xT[g_col[p] * 96 + k], acc);
    g_AX[i * 96 + k] = acc;
}

__global__ void zero_kernel() {
    const int idx = blockIdx.x * blockDim.x + threadIdx.x;
    if (idx < NN * HH) {
        g_h0[0][idx] = 0.0f; g_c0[0][idx] = 0.0f;
        g_h1[0][idx] = 0.0f; g_c1[0][idx] = 0.0f;
    }
}

// ---------------- cell bodies ----------------------------------------------------
// Shared buffer union (floats), 16B aligned:
//   cell0: sAh[32][64]@0, sH[32][64]@2048, sXA[32][2]@4096, sXI[32][2]@4160,
//          scol[2048]@4224(int), sval[2048]@6272       -> 8320 floats (33.3 KB)
//   cell1: sAi[16][64]@0, sAh[16][64]@1024, sI[16][64]@2048, sH[16][64]@3072,
//          scol[1024]@4096(int), sval[1024]@5120       -> fits in same buffer
#define SBUF_F 8320

__device__ __forceinline__ void cell0_body(
    float* __restrict__ sbuf, int row0, int t,
    const float* __restrict__ h_in, const float* __restrict__ c_in,
    float* __restrict__ h_out, float* __restrict__ c_out,
    const float* __restrict__ Wgi, const float* __restrict__ Wgh,
    const float* __restrict__ Wli, const float* __restrict__ Wlh,
    const float* __restrict__ bgi, const float* __restrict__ bgh,
    const float* __restrict__ bli, const float* __restrict__ blh)
{
    const int tid = threadIdx.x;
    const int m   = tid & 63;
    const int rg  = tid >> 6;

    float* sAh  = sbuf;           // [32][64]
    float* sH   = sbuf + 2048;    // [32][64]
    float* sXA  = sbuf + 4096;    // [32][2]
    float* sXI  = sbuf + 4160;    // [32][2]
    int*   scol = (int*)(sbuf + 4224);   // [CAP0]
    float* sval = sbuf + 6272;           // [CAP0]

    // Stage this block's CSR segment into smem (coalesced, high MLP)
    const int base = g_rowptr[row0];
    const int tot  = g_rowptr[row0 + RT0] - base;
    const int nst  = (tot < CAP0) ? tot : CAP0;
    for (int q = tid; q < nst; q += 256) {
        scol[q] = g_col[base + q];
        sval[q] = g_val[base + q];
    }
    __syncthreads();

    // Gather phase: deep-unrolled independent gathers (MLP ~8)
    for (int r = rg; r < RT0; r += 4) {
        const int i = row0 + r;
        sH[r * 64 + m] = __ldg(&h_in[i * HH + m]);
        int       p  = g_rowptr[i]     - base;
        const int pe = g_rowptr[i + 1] - base;
        const int ps = (pe < CAP0) ? pe : CAP0;
        float a0 = 0.0f, a1 = 0.0f, a2 = 0.0f, a3 = 0.0f;
        for (; p + 8 <= ps; p += 8) {
            const int   c0 = scol[p    ], c1 = scol[p + 1];
            const int   c2 = scol[p + 2], c3 = scol[p + 3];
            const int   c4 = scol[p + 4], c5 = scol[p + 5];
            const int   c6 = scol[p + 6], c7 = scol[p + 7];
            const float v0 = sval[p    ], v1 = sval[p + 1];
            const float v2 = sval[p + 2], v3 = sval[p + 3];
            const float v4 = sval[p + 4], v5 = sval[p + 5];
            const float v6 = sval[p + 6], v7 = sval[p + 7];
            a0 = fmaf(v0, __ldg(&h_in[c0 * HH + m]), a0);
            a1 = fmaf(v1, __ldg(&h_in[c1 * HH + m]), a1);
            a2 = fmaf(v2, __ldg(&h_in[c2 * HH + m]), a2);
            a3 = fmaf(v3, __ldg(&h_in[c3 * HH + m]), a3);
            a0 = fmaf(v4, __ldg(&h_in[c4 * HH + m]), a0);
            a1 = fmaf(v5, __ldg(&h_in[c5 * HH + m]), a1);
            a2 = fmaf(v6, __ldg(&h_in[c6 * HH + m]), a2);
            a3 = fmaf(v7, __ldg(&h_in[c7 * HH + m]), a3);
        }
        for (; p < ps; ++p)
            a0 = fmaf(sval[p], __ldg(&h_in[scol[p] * HH + m]), a0);
        for (; p < pe; ++p)   // overflow fallback (exact; normally never runs)
            a0 = fmaf(g_val[base + p], __ldg(&h_in[g_col[base + p] * HH + m]), a0);
        sAh[r * 64 + m] = (a0 + a1) + (a2 + a3);
        if (m < 2) {
            sXA[r * 2 + m] = g_AX[i * 96 + 2 * t + m];
            sXI[r * 2 + m] = g_xT[i * 96 + 2 * t + m];
        }
    }
    __syncthreads();

    const int kk = m;
    const int rbase = rg * 8;

    float ai[8], af[8], ao[8], ag[8];
    {
        const float b0 = __ldg(&bgi[kk      ]) + __ldg(&bgh[kk      ]) + __ldg(&bli[kk      ]) + __ldg(&blh[kk      ]);
        const float b1 = __ldg(&bgi[kk +  64]) + __ldg(&bgh[kk +  64]) + __ldg(&bli[kk +  64]) + __ldg(&blh[kk +  64]);
        const float b2 = __ldg(&bgi[kk + 128]) + __ldg(&bgh[kk + 128]) + __ldg(&bli[kk + 128]) + __ldg(&blh[kk + 128]);
        const float b3 = __ldg(&bgi[kk + 192]) + __ldg(&bgh[kk + 192]) + __ldg(&bli[kk + 192]) + __ldg(&blh[kk + 192]);
#pragma unroll
        for (int r = 0; r < 8; ++r) { ai[r] = b0; af[r] = b1; ao[r] = b2; ag[r] = b3; }
    }

#define C0_ACC(W, S)                                                         \
    for (int mm = 0; mm < HH; mm += 4) {                                     \
        float w0[4], w1[4], w2[4], w3[4];                                    \
        _Pragma("unroll")                                                    \
        for (int u = 0; u < 4; ++u) {                                        \
            w0[u] = __ldg(&W[(mm + u) * G4 + kk      ]);                     \
            w1[u] = __ldg(&W[(mm + u) * G4 + kk +  64]);                     \
            w2[u] = __ldg(&W[(mm + u) * G4 + kk + 128]);                     \
            w3[u] = __ldg(&W[(mm + u) * G4 + kk + 192]);                     \
        }                                                                    \
        _Pragma("unroll")                                                    \
        for (int r = 0; r < 8; ++r) {                                        \
            const float4 v = *(const float4*)&S[(rbase + r) * 64 + mm];      \
            ai[r] = fmaf(v.x, w0[0], ai[r]); af[r] = fmaf(v.x, w1[0], af[r]);\
            ao[r] = fmaf(v.x, w2[0], ao[r]); ag[r] = fmaf(v.x, w3[0], ag[r]);\
            ai[r] = fmaf(v.y, w0[1], ai[r]); af[r] = fmaf(v.y, w1[1], af[r]);\
            ao[r] = fmaf(v.y, w2[1], ao[r]); ag[r] = fmaf(v.y, w3[1], ag[r]);\
            ai[r] = fmaf(v.z, w0[2], ai[r]); af[r] = fmaf(v.z, w1[2], af[r]);\
            ao[r] = fmaf(v.z, w2[2], ao[r]); ag[r] = fmaf(v.z, w3[2], ag[r]);\
            ai[r] = fmaf(v.w, w0[3], ai[r]); af[r] = fmaf(v.w, w1[3], af[r]);\
            ao[r] = fmaf(v.w, w2[3], ao[r]); ag[r] = fmaf(v.w, w3[3], ag[r]);\
        }                                                                    \
    }

    C0_ACC(Wgh, sAh)
    C0_ACC(Wlh, sH)
#undef C0_ACC

#pragma unroll
    for (int mm = 0; mm < INW; ++mm) {
        const float w0 = __ldg(&Wgi[mm * G4 + kk      ]);
        const float w1 = __ldg(&Wgi[mm * G4 + kk +  64]);
        const float w2 = __ldg(&Wgi[mm * G4 + kk + 128]);
        const float w3 = __ldg(&Wgi[mm * G4 + kk + 192]);
        const float u0 = __ldg(&Wli[mm * G4 + kk      ]);
        const float u1 = __ldg(&Wli[mm * G4 + kk +  64]);
        const float u2 = __ldg(&Wli[mm * G4 + kk + 128]);
        const float u3 = __ldg(&Wli[mm * G4 + kk + 192]);
#pragma unroll
        for (int r = 0; r < 8; ++r) {
            const float va = sXA[(rbase + r) * 2 + mm];
            const float vi = sXI[(rbase + r) * 2 + mm];
            ai[r] = fmaf(va, w0, ai[r]); af[r] = fmaf(va, w1, af[r]);
            ao[r] = fmaf(va, w2, ao[r]); ag[r] = fmaf(va, w3, ag[r]);
            ai[r] = fmaf(vi, u0, ai[r]); af[r] = fmaf(vi, u1, af[r]);
            ao[r] = fmaf(vi, u2, ao[r]); ag[r] = fmaf(vi, u3, ag[r]);
        }
    }

#pragma unroll
    for (int r = 0; r < 8; ++r) {
        const int i = row0 + rbase + r;
        const float cold = __ldg(&c_in[i * HH + kk]);
        const float igt = sigm(ai[r]);
        const float fgt = sigm(af[r]);
        const float ogt = sigm(ao[r]);
        const float ggt = tanhf(ag[r]);
        const float cn = fgt * cold + igt * ggt;
        c_out[i * HH + kk] = cn;
        h_out[i * HH + kk] = ogt * tanhf(cn);
    }
}

__device__ __forceinline__ void cell1_body(
    float* __restrict__ sbuf, int row0,
    const float* __restrict__ inp,  const float* __restrict__ h_in,
    const float* __restrict__ c_in,
    float* __restrict__ h_out, float* __restrict__ c_out,
    const float* __restrict__ Wgi, const float* __restrict__ Wgh,
    const float* __restrict__ Wli, const float* __restrict__ Wlh,
    const float* __restrict__ bgi, const float* __restrict__ bgh,
    const float* __restrict__ bli, const float* __restrict__ blh)
{
    const int tid = threadIdx.x;
    const int m   = tid & 63;
    const int rg  = tid >> 6;

    float* sAi  = sbuf;           // [16][64]
    float* sAh  = sbuf + 1024;
    float* sI   = sbuf + 2048;
    float* sH   = sbuf + 3072;
    int*   scol = (int*)(sbuf + 4096);   // [CAP1]
    float* sval = sbuf + 5120;           // [CAP1]

    // Stage this block's CSR segment into smem
    const int base = g_rowptr[row0];
    const int tot  = g_rowptr[row0 + RT1] - base;
    const int nst  = (tot < CAP1) ? tot : CAP1;
    for (int q = tid; q < nst; q += 256) {
        scol[q] = g_col[base + q];
        sval[q] = g_val[base + q];
    }
    __syncthreads();

    for (int r = rg; r < RT1; r += 4) {
        const int i = row0 + r;
        sI[r * 64 + m] = __ldg(&inp [i * HH + m]);
        sH[r * 64 + m] = __ldg(&h_in[i * HH + m]);
        int       p  = g_rowptr[i]     - base;
        const int pe = g_rowptr[i + 1] - base;
        const int ps = (pe < CAP1) ? pe : CAP1;
        float a0 = 0.0f, a1 = 0.0f, a2 = 0.0f, a3 = 0.0f;
        float b0 = 0.0f, b1 = 0.0f, b2 = 0.0f, b3 = 0.0f;
        for (; p + 4 <= ps; p += 4) {
            const int   c0 = scol[p    ], c1 = scol[p + 1];
            const int   c2 = scol[p + 2], c3 = scol[p + 3];
            const float v0 = sval[p    ], v1 = sval[p + 1];
            const float v2 = sval[p + 2], v3 = sval[p + 3];
            a0 = fmaf(v0, __ldg(&inp [c0 * HH + m]), a0);
            b0 = fmaf(v0, __ldg(&h_in[c0 * HH + m]), b0);
            a1 = fmaf(v1, __ldg(&inp [c1 * HH + m]), a1);
            b1 = fmaf(v1, __ldg(&h_in[c1 * HH + m]), b1);
            a2 = fmaf(v2, __ldg(&inp [c2 * HH + m]), a2);
            b2 = fmaf(v2, __ldg(&h_in[c2 * HH + m]), b2);
            a3 = fmaf(v3, __ldg(&inp [c3 * HH + m]), a3);
            b3 = fmaf(v3, __ldg(&h_in[c3 * HH + m]), b3);
        }
        for (; p < ps; ++p) {
            const int   c = scol[p];
            const float v = sval[p];
            a0 = fmaf(v, __ldg(&inp [c * HH + m]), a0);
            b0 = fmaf(v, __ldg(&h_in[c * HH + m]), b0);
        }
        for (; p < pe; ++p) {  // overflow fallback (exact; normally never runs)
            const int   c = g_col[base + p];
            const float v = g_val[base + p];
            a0 = fmaf(v, __ldg(&inp [c * HH + m]), a0);
            b0 = fmaf(v, __ldg(&h_in[c * HH + m]), b0);
        }
        sAi[r * 64 + m] = (a0 + a1) + (a2 + a3);
        sAh[r * 64 + m] = (b0 + b1) + (b2 + b3);
    }
    __syncthreads();

    const int kk = m;
    const int rbase = rg * 4;

    float ai[4], af[4], ao[4], ag[4];
    {
        const float b0 = __ldg(&bgi[kk      ]) + __ldg(&bgh[kk      ]) + __ldg(&bli[kk      ]) + __ldg(&blh[kk      ]);
        const float b1 = __ldg(&bgi[kk +  64]) + __ldg(&bgh[kk +  64]) + __ldg(&bli[kk +  64]) + __ldg(&blh[kk +  64]);
        const float b2 = __ldg(&bgi[kk + 128]) + __ldg(&bgh[kk + 128]) + __ldg(&bli[kk + 128]) + __ldg(&blh[kk + 128]);
        const float b3 = __ldg(&bgi[kk + 192]) + __ldg(&bgh[kk + 192]) + __ldg(&bli[kk + 192]) + __ldg(&blh[kk + 192]);
#pragma unroll
        for (int r = 0; r < 4; ++r) { ai[r] = b0; af[r] = b1; ao[r] = b2; ag[r] = b3; }
    }

#define C1_ACC(W, S)                                                         \
    for (int mm = 0; mm < HH; mm += 4) {                                     \
        float w0[4], w1[4], w2[4], w3[4];                                    \
        _Pragma("unroll")                                                    \
        for (int u = 0; u < 4; ++u) {                                        \
            w0[u] = __ldg(&W[(mm + u) * G4 + kk      ]);                     \
            w1[u] = __ldg(&W[(mm + u) * G4 + kk +  64]);                     \
            w2[u] = __ldg(&W[(mm + u) * G4 + kk + 128]);                     \
            w3[u] = __ldg(&W[(mm + u) * G4 + kk + 192]);                     \
        }                                                                    \
        _Pragma("unroll")                                                    \
        for (int r = 0; r < 4; ++r) {                                        \
            const float4 v = *(const float4*)&S[(rbase + r) * 64 + mm];      \
            ai[r] = fmaf(v.x, w0[0], ai[r]); af[r] = fmaf(v.x, w1[0], af[r]);\
            ao[r] = fmaf(v.x, w2[0], ao[r]); ag[r] = fmaf(v.x, w3[0], ag[r]);\
            ai[r] = fmaf(v.y, w0[1], ai[r]); af[r] = fmaf(v.y, w1[1], af[r]);\
            ao[r] = fmaf(v.y, w2[1], ao[r]); ag[r] = fmaf(v.y, w3[1], ag[r]);\
            ai[r] = fmaf(v.z, w0[2], ai[r]); af[r] = fmaf(v.z, w1[2], af[r]);\
            ao[r] = fmaf(v.z, w2[2], ao[r]); ag[r] = fmaf(v.z, w3[2], ag[r]);\
            ai[r] = fmaf(v.w, w0[3], ai[r]); af[r] = fmaf(v.w, w1[3], af[r]);\
            ao[r] = fmaf(v.w, w2[3], ao[r]); ag[r] = fmaf(v.w, w3[3], ag[r]);\
        }                                                                    \
    }

    C1_ACC(Wgi, sAi)
    C1_ACC(Wgh, sAh)
    C1_ACC(Wli, sI)
    C1_ACC(Wlh, sH)
#undef C1_ACC

#pragma unroll
    for (int r = 0; r < 4; ++r) {
        const int i = row0 + rbase + r;
        const float cold = __ldg(&c_in[i * HH + kk]);
        const float igt = sigm(ai[r]);
        const float fgt = sigm(af[r]);
        const float ogt = sigm(ao[r]);
        const float ggt = tanhf(ag[r]);
        const float cn = fgt * cold + igt * ggt;
        c_out[i * HH + kk] = cn;
        h_out[i * HH + kk] = ogt * tanhf(cn);
    }
}

// ---------------- kernels --------------------------------------------------------

// Standalone cell0 (first step only)
__global__ void __launch_bounds__(256, 2) cell0_kernel(
    int t, int rd,
    const float* __restrict__ Wgi, const float* __restrict__ Wgh,
    const float* __restrict__ Wli, const float* __restrict__ Wlh,
    const float* __restrict__ bgi, const float* __restrict__ bgh,
    const float* __restrict__ bli, const float* __restrict__ blh)
{
    __shared__ __align__(16) float sbuf[SBUF_F];
    cell0_body(sbuf, blockIdx.x * RT0, t,
               g_h0[rd], g_c0[rd], g_h0[rd ^ 1], g_c0[rd ^ 1],
               Wgi, Wgh, Wli, Wlh, bgi, bgh, bli, blh);
}

// Standalone cell1 (last step only)
__global__ void __launch_bounds__(256, 2) cell1_kernel(
    int rd,
    const float* __restrict__ Wgi, const float* __restrict__ Wgh,
    const float* __restrict__ Wli, const float* __restrict__ Wlh,
    const float* __restrict__ bgi, const float* __restrict__ bgh,
    const float* __restrict__ bli, const float* __restrict__ blh)
{
    __shared__ __align__(16) float sbuf[SBUF_F];
    cell1_body(sbuf, blockIdx.x * RT1,
               g_h0[rd ^ 1], g_h1[rd], g_c1[rd], g_h1[rd ^ 1], g_c1[rd ^ 1],
               Wgi, Wgh, Wli, Wlh, bgi, bgh, bli, blh);
}

// Fused: cell1(tnext-1) runs concurrently with cell0(tnext).
// Both read h0 written at step tnext-1 (buffer rd0); cell0 writes h0[rd0^1],
// cell1 writes h1[rd1^1]. No buffer is both read and written across roles.
__global__ void __launch_bounds__(256, 2) step_kernel(
    int tnext,
    const float* __restrict__ Wgi0, const float* __restrict__ Wgh0,
    const float* __restrict__ Wli0, const float* __restrict__ Wlh0,
    const float* __restrict__ bgi0, const float* __restrict__ bgh0,
    const float* __restrict__ bli0, const float* __restrict__ blh0,
    const float* __restrict__ Wgi1, const float* __restrict__ Wgh1,
    const float* __restrict__ Wli1, const float* __restrict__ Wlh1,
    const float* __restrict__ bgi1, const float* __restrict__ bgh1,
    const float* __restrict__ bli1, const float* __restrict__ blh1)
{
    __shared__ __align__(16) float sbuf[SBUF_F];
    const int rd0 = tnext & 1;         // cell0 parity at step tnext
    const int rd1 = rd0 ^ 1;           // cell1 parity at step tnext-1
    if (blockIdx.x < NB0) {
        cell0_body(sbuf, blockIdx.x * RT0, tnext,
                   g_h0[rd0], g_c0[rd0], g_h0[rd0 ^ 1], g_c0[rd0 ^ 1],
                   Wgi0, Wgh0, Wli0, Wlh0, bgi0, bgh0, bli0, blh0);
    } else {
        cell1_body(sbuf, (blockIdx.x - NB0) * RT1,
                   g_h0[rd0],                  // inp = h0(tnext-1)
                   g_h1[rd1], g_c1[rd1], g_h1[rd1 ^ 1], g_c1[rd1 ^ 1],
                   Wgi1, Wgh1, Wli1, Wlh1, bgi1, bgh1, bli1, blh1);
    }
}

// Final projection: out[i,p] = h1[i,:] @ outW[:,p] + outb[p]
__global__ void out_kernel(const float* __restrict__ outW,
                           const float* __restrict__ outb,
                           float* __restrict__ out)
{
    const int idx = blockIdx.x * blockDim.x + threadIdx.x;
    if (idx >= NN * PP) return;
    const int i = idx / PP;
    const int p = idx % PP;
    const float* h = &g_h1[0][i * HH];   // parity 0 after 48 steps
    float acc = __ldg(&outb[p]);
#pragma unroll
    for (int mm = 0; mm < HH; ++mm)
        acc = fmaf(h[mm], __ldg(&outW[mm * PP + p]), acc);
    out[idx] = acc;
}

// ---------------- launch --------------------------------------------------------
extern "C" void kernel_launch(void* const* d_in, const int* in_sizes, int n_in,
                              void* d_out, int out_size) {
    const float* x     = (const float*)d_in[0];
    const float* adj   = (const float*)d_in[1];
    const float* gcWi0 = (const float*)d_in[2];  const float* gcbi0 = (const float*)d_in[3];
    const float* gcWh0 = (const float*)d_in[4];  const float* gcbh0 = (const float*)d_in[5];
    const float* liWi0 = (const float*)d_in[6];  const float* libi0 = (const float*)d_in[7];
    const float* liWh0 = (const float*)d_in[8];  const float* libh0 = (const float*)d_in[9];
    const float* gcWi1 = (const float*)d_in[10]; const float* gcbi1 = (const float*)d_in[11];
    const float* gcWh1 = (const float*)d_in[12]; const float* gcbh1 = (const float*)d_in[13];
    const float* liWi1 = (const float*)d_in[14]; const float* libi1 = (const float*)d_in[15];
    const float* liWh1 = (const float*)d_in[16]; const float* libh1 = (const float*)d_in[17];
    const float* outW  = (const float*)d_in[18]; const float* outb  = (const float*)d_in[19];
    float* out = (float*)d_out;

    // Preprocessing (captured in the graph; deterministic)
    degree_kernel<<<NN, 128>>>(adj);
    scan_kernel<<<1, 1024>>>();
    fill_kernel<<<(NN * 32 + 255) / 256, 256>>>(adj);
    xT_kernel<<<(NN * 96 + 255) / 256, 256>>>(x);
    ax_kernel<<<NN, 96>>>();
    zero_kernel<<<(NN * HH + 255) / 256, 256>>>();

    // Step 0: cell0 alone (reads zeroed h0[0], writes h0[1])
    cell0_kernel<<<NB0, 256>>>(0, 0,
        gcWi0, gcWh0, liWi0, liWh0, gcbi0, gcbh0, libi0, libh0);

    // Steps: fused cell1(t-1) || cell0(t) for t = 1..47
    for (int tnext = 1; tnext < TT; ++tnext) {
        step_kernel<<<NB0 + NB1, 256>>>(tnext,
            gcWi0, gcWh0, liWi0, liWh0, gcbi0, gcbh0, libi0, libh0,
            gcWi1, gcWh1, liWi1, liWh1, gcbi1, gcbh1, libi1, libh1);
    }

    // Last: cell1 for step 47 (rd = 47 & 1 = 1)
    cell1_kernel<<<NB1, 256>>>(1,
        gcWi1, gcWh1, liWi1, liWh1, gcbi1, gcbh1, libi1, libh1);

    out_kernel<<<(NN * PP + 255) / 256, 256>>>(outW, outb, out);
}

// round 10
// speedup vs baseline: 1.7628x; 1.2657x over previous
#include <cuda_runtime.h>
#include <cuda_bf16.h>
#include <math.h>

// Problem constants
#define NN    4096          // graph nodes
#define TT    48            // timesteps
#define HH    64            // hidden
#define INW   2             // input width
#define PP    12            // output width
#define G4    256           // 4*H
#define RT0   32            // rows per block, cell0
#define RT1   16            // rows per block, cell1
#define NB0   (NN / RT0)    // 128 blocks for cell0
#define NB1   (NN / RT1)    // 256 blocks for cell1
#define CAP0  2048          // staged nnz cap, cell0 (expected ~1344/block)
#define CAP1  1024          // staged nnz cap, cell1 (expected ~672/block)

#define NNZ_MAX (1 << 19)

// ---------------- device scratch -------------------------------------------------
__device__ int   g_rowptr[NN + 1];
__device__ int   g_rowcnt[NN];
__device__ int   g_col[NNZ_MAX];
__device__ float g_val[NNZ_MAX];
__device__ float g_dinv[NN];
__device__ float g_xT[NN * 96];   // x transposed: [node][t*2+c]
__device__ float g_AX[NN * 96];   // A @ x, same layout
__device__ float g_h0[2][NN * HH];
__device__ float g_c0[2][NN * HH];
__device__ float g_h1[2][NN * HH];
__device__ float g_c1[2][NN * HH];

__device__ __forceinline__ float sigm(float x) { return 1.0f / (1.0f + expf(-x)); }

// ---------------- preprocessing -------------------------------------------------
__global__ void degree_kernel(const float* __restrict__ adj) {
    const int i = blockIdx.x;
    const int tid = threadIdx.x;
    const float* row = adj + (size_t)i * NN;
    float d = 0.0f;
    int cnt = 0;
    for (int j = tid; j < NN; j += blockDim.x) {
        const float a = __ldg(&row[j]);
        d += a;
        cnt += (a != 0.0f && j != i) ? 1 : 0;
    }
    __shared__ float sd[128];
    __shared__ int   sc[128];
    sd[tid] = d; sc[tid] = cnt;
    __syncthreads();
    for (int off = 64; off > 0; off >>= 1) {
        if (tid < off) { sd[tid] += sd[tid + off]; sc[tid] += sc[tid + off]; }
        __syncthreads();
    }
    if (tid == 0) {
        const float dd = sd[0] + 1.0f;
        g_dinv[i]   = 1.0f / sqrtf(dd);
        g_rowcnt[i] = sc[0] + 1;
    }
}

__global__ void scan_kernel() {
    __shared__ int s[1024];
    const int tid = threadIdx.x;
    int c[4];
    int sum = 0;
#pragma unroll
    for (int u = 0; u < 4; ++u) { c[u] = g_rowcnt[tid * 4 + u]; sum += c[u]; }
    s[tid] = sum;
    __syncthreads();
    for (int off = 1; off < 1024; off <<= 1) {
        const int v = (tid >= off) ? s[tid - off] : 0;
        __syncthreads();
        s[tid] += v;
        __syncthreads();
    }
    int excl = s[tid] - sum;
#pragma unroll
    for (int u = 0; u < 4; ++u) { g_rowptr[tid * 4 + u] = excl; excl += c[u]; }
    if (tid == 1023) g_rowptr[NN] = s[1023];
}

__global__ void fill_kernel(const float* __restrict__ adj) {
    const int w = (blockIdx.x * blockDim.x + threadIdx.x) >> 5;
    const int lane = threadIdx.x & 31;
    if (w >= NN) return;
    const int i = w;
    const float* row = adj + (size_t)i * NN;
    const float di = g_dinv[i];
    int base = g_rowptr[i];
    for (int j0 = 0; j0 < NN; j0 += 32) {
        const int j = j0 + lane;
        const float a = __ldg(&row[j]);
        const bool pred = (a != 0.0f) || (j == i);
        const unsigned mask = __ballot_sync(0xffffffffu, pred);
        if (pred) {
            const int idx = base + __popc(mask & ((1u << lane) - 1u));
            if (idx < NNZ_MAX) {
                g_col[idx] = j;
                const float v = a + ((j == i) ? 1.0f : 0.0f);
                g_val[idx] = di * g_dinv[j] * v;
            }
        }
        base += __popc(mask);
    }
}

__global__ void xT_kernel(const float* __restrict__ x) {
    const int idx = blockIdx.x * blockDim.x + threadIdx.x;
    if (idx >= NN * 96) return;
    const int n = idx / 96;
    const int k = idx % 96;
    const int t = k >> 1;
    const int c = k & 1;
    g_xT[idx] = __ldg(&x[t * (NN * INW) + n * INW + c]);
}

__global__ void ax_kernel() {
    const int i = blockIdx.x;
    const int k = threadIdx.x;  // 0..95
    const int p0 = g_rowptr[i], p1 = g_rowptr[i + 1];
    float acc = 0.0f;
    for (int p = p0; p < p1; ++p)
        acc = fmaf(g_val[p], g_xT[g_col[p] * 96 + k], acc);
    g_AX[i * 96 + k] = acc;
}

__global__ void zero_kernel() {
    const int idx = blockIdx.x * blockDim.x + threadIdx.x;
    if (idx < NN * HH) {
        g_h0[0][idx] = 0.0f; g_c0[0][idx] = 0.0f;
        g_h1[0][idx] = 0.0f; g_c1[0][idx] = 0.0f;
    }
}

// ---------------- cell bodies ----------------------------------------------------
// Shared buffer union (floats), 16B aligned; SBUF_F = 8320 (33.3 KB):
//   cell0: sAh[32][64]@0, sH[32][64]@2048, sXA[32][2]@4096, sXI[32][2]@4160,
//          U@4224: { scol[2048](int) + sval[2048]@6272 } OR comb[8][256]@4224
//   cell1: sAi[16][64]@0, sAh@1024, sI@2048, sH@3072,
//          U@4096: { scol[1024](int) + sval[1024]@5120 } OR comb[8][256]@4096
// CSR staging is dead after the gather phase; comb overlays it.
#define SBUF_F 8320

__device__ __forceinline__ void cell0_body(
    float* __restrict__ sbuf, int row0, int t,
    const float* __restrict__ h_in, const float* __restrict__ c_in,
    float* __restrict__ h_out, float* __restrict__ c_out,
    const float* __restrict__ Wgi, const float* __restrict__ Wgh,
    const float* __restrict__ Wli, const float* __restrict__ Wlh,
    const float* __restrict__ bgi, const float* __restrict__ bgh,
    const float* __restrict__ bli, const float* __restrict__ blh)
{
    const int tid = threadIdx.x;
    const int m   = tid & 63;
    const int rg  = tid >> 6;

    float* sAh  = sbuf;           // [32][64]
    float* sH   = sbuf + 2048;    // [32][64]
    float* sXA  = sbuf + 4096;    // [32][2]
    float* sXI  = sbuf + 4160;    // [32][2]
    int*   scol = (int*)(sbuf + 4224);   // [CAP0]
    float* sval = sbuf + 6272;           // [CAP0]
    float* scomb = sbuf + 4224;          // [8][256], overlays CSR after gather

    // Stage this block's CSR segment into smem (coalesced, high MLP)
    const int base = g_rowptr[row0];
    const int tot  = g_rowptr[row0 + RT0] - base;
    const int nst  = (tot < CAP0) ? tot : CAP0;
    for (int q = tid; q < nst; q += 256) {
        scol[q] = g_col[base + q];
        sval[q] = g_val[base + q];
    }
    __syncthreads();

    // Gather phase: deep-unrolled independent gathers (MLP ~8)
    for (int r = rg; r < RT0; r += 4) {
        const int i = row0 + r;
        sH[r * 64 + m] = __ldg(&h_in[i * HH + m]);
        int       p  = g_rowptr[i]     - base;
        const int pe = g_rowptr[i + 1] - base;
        const int ps = (pe < CAP0) ? pe : CAP0;
        float a0 = 0.0f, a1 = 0.0f, a2 = 0.0f, a3 = 0.0f;
        for (; p + 8 <= ps; p += 8) {
            const int   c0 = scol[p    ], c1 = scol[p + 1];
            const int   c2 = scol[p + 2], c3 = scol[p + 3];
            const int   c4 = scol[p + 4], c5 = scol[p + 5];
            const int   c6 = scol[p + 6], c7 = scol[p + 7];
            const float v0 = sval[p    ], v1 = sval[p + 1];
            const float v2 = sval[p + 2], v3 = sval[p + 3];
            const float v4 = sval[p + 4], v5 = sval[p + 5];
            const float v6 = sval[p + 6], v7 = sval[p + 7];
            a0 = fmaf(v0, __ldg(&h_in[c0 * HH + m]), a0);
            a1 = fmaf(v1, __ldg(&h_in[c1 * HH + m]), a1);
            a2 = fmaf(v2, __ldg(&h_in[c2 * HH + m]), a2);
            a3 = fmaf(v3, __ldg(&h_in[c3 * HH + m]), a3);
            a0 = fmaf(v4, __ldg(&h_in[c4 * HH + m]), a0);
            a1 = fmaf(v5, __ldg(&h_in[c5 * HH + m]), a1);
            a2 = fmaf(v6, __ldg(&h_in[c6 * HH + m]), a2);
            a3 = fmaf(v7, __ldg(&h_in[c7 * HH + m]), a3);
        }
        for (; p < ps; ++p)
            a0 = fmaf(sval[p], __ldg(&h_in[scol[p] * HH + m]), a0);
        for (; p < pe; ++p)   // overflow fallback (exact; normally never runs)
            a0 = fmaf(g_val[base + p], __ldg(&h_in[g_col[base + p] * HH + m]), a0);
        sAh[r * 64 + m] = (a0 + a1) + (a2 + a3);
        if (m < 2) {
            sXA[r * 2 + m] = g_AX[i * 96 + 2 * t + m];
            sXI[r * 2 + m] = g_xT[i * 96 + 2 * t + m];
        }
    }
    __syncthreads();

    // GEMM phase: thread owns gate-column kk2 = tid for ALL 32 rows.
    // Every weight element loaded exactly once per block (coalesced 128B/warp).
    const int kk2 = tid;
    float acc[RT0];
    {
        const float bb = __ldg(&bgi[kk2]) + __ldg(&bgh[kk2]) + __ldg(&bli[kk2]) + __ldg(&blh[kk2]);
#pragma unroll
        for (int r = 0; r < RT0; ++r) acc[r] = bb;
    }

#pragma unroll 1
    for (int mm = 0; mm < HH; mm += 4) {
        const float w0 = __ldg(&Wgh[(mm + 0) * G4 + kk2]);
        const float w1 = __ldg(&Wgh[(mm + 1) * G4 + kk2]);
        const float w2 = __ldg(&Wgh[(mm + 2) * G4 + kk2]);
        const float w3 = __ldg(&Wgh[(mm + 3) * G4 + kk2]);
        const float u0 = __ldg(&Wlh[(mm + 0) * G4 + kk2]);
        const float u1 = __ldg(&Wlh[(mm + 1) * G4 + kk2]);
        const float u2 = __ldg(&Wlh[(mm + 2) * G4 + kk2]);
        const float u3 = __ldg(&Wlh[(mm + 3) * G4 + kk2]);
#pragma unroll
        for (int r = 0; r < RT0; ++r) {
            const float4 va = *(const float4*)&sAh[r * 64 + mm];
            const float4 vh = *(const float4*)&sH [r * 64 + mm];
            acc[r] = fmaf(va.x, w0, acc[r]); acc[r] = fmaf(va.y, w1, acc[r]);
            acc[r] = fmaf(va.z, w2, acc[r]); acc[r] = fmaf(va.w, w3, acc[r]);
            acc[r] = fmaf(vh.x, u0, acc[r]); acc[r] = fmaf(vh.y, u1, acc[r]);
            acc[r] = fmaf(vh.z, u2, acc[r]); acc[r] = fmaf(vh.w, u3, acc[r]);
        }
    }
    {   // input terms (K = 2 each)
        const float wa0 = __ldg(&Wgi[0 * G4 + kk2]);
        const float wa1 = __ldg(&Wgi[1 * G4 + kk2]);
        const float wi0 = __ldg(&Wli[0 * G4 + kk2]);
        const float wi1 = __ldg(&Wli[1 * G4 + kk2]);
#pragma unroll
        for (int r = 0; r < RT0; ++r) {
            const float2 xa = *(const float2*)&sXA[r * 2];
            const float2 xi = *(const float2*)&sXI[r * 2];
            acc[r] = fmaf(xa.x, wa0, acc[r]); acc[r] = fmaf(xa.y, wa1, acc[r]);
            acc[r] = fmaf(xi.x, wi0, acc[r]); acc[r] = fmaf(xi.y, wi1, acc[r]);
        }
    }

    // Elementwise phase: exchange pre-activations in 8-row chunks via scomb.
#pragma unroll
    for (int r0 = 0; r0 < RT0; r0 += 8) {
        __syncthreads();   // scomb free (CSR dead / previous chunk consumed)
#pragma unroll
        for (int rr = 0; rr < 8; ++rr)
            scomb[rr * 256 + kk2] = acc[r0 + rr];
        __syncthreads();
        const int rw = tid >> 5;             // warp w -> row r0+w
        const int hh = (tid & 31) * 2;       // 2 hidden units per lane
        const int i  = row0 + r0 + rw;
        const float2 ci = *(const float2*)&scomb[rw * 256 + hh      ];
        const float2 cf = *(const float2*)&scomb[rw * 256 + hh +  64];
        const float2 co = *(const float2*)&scomb[rw * 256 + hh + 128];
        const float2 cg = *(const float2*)&scomb[rw * 256 + hh + 192];
        const float2 cold = *(const float2*)&c_in[i * HH + hh];
        float2 cn, hn;
        cn.x = sigm(cf.x) * cold.x + sigm(ci.x) * tanhf(cg.x);
        cn.y = sigm(cf.y) * cold.y + sigm(ci.y) * tanhf(cg.y);
        hn.x = sigm(co.x) * tanhf(cn.x);
        hn.y = sigm(co.y) * tanhf(cn.y);
        *(float2*)&c_out[i * HH + hh] = cn;
        *(float2*)&h_out[i * HH + hh] = hn;
    }
}

__device__ __forceinline__ void cell1_body(
    float* __restrict__ sbuf, int row0,
    const float* __restrict__ inp,  const float* __restrict__ h_in,
    const float* __restrict__ c_in,
    float* __restrict__ h_out, float* __restrict__ c_out,
    const float* __restrict__ Wgi, const float* __restrict__ Wgh,
    const float* __restrict__ Wli, const float* __restrict__ Wlh,
    const float* __restrict__ bgi, const float* __restrict__ bgh,
    const float* __restrict__ bli, const float* __restrict__ blh)
{
    const int tid = threadIdx.x;
    const int m   = tid & 63;
    const int rg  = tid >> 6;

    float* sAi  = sbuf;           // [16][64]
    float* sAh  = sbuf + 1024;
    float* sI   = sbuf + 2048;
    float* sH   = sbuf + 3072;
    int*   scol = (int*)(sbuf + 4096);   // [CAP1]
    float* sval = sbuf + 5120;           // [CAP1]
    float* scomb = sbuf + 4096;          // [8][256], overlays CSR after gather

    // Stage this block's CSR segment into smem
    const int base = g_rowptr[row0];
    const int tot  = g_rowptr[row0 + RT1] - base;
    const int nst  = (tot < CAP1) ? tot : CAP1;
    for (int q = tid; q < nst; q += 256) {
        scol[q] = g_col[base + q];
        sval[q] = g_val[base + q];
    }
    __syncthreads();

    for (int r = rg; r < RT1; r += 4) {
        const int i = row0 + r;
        sI[r * 64 + m] = __ldg(&inp [i * HH + m]);
        sH[r * 64 + m] = __ldg(&h_in[i * HH + m]);
        int       p  = g_rowptr[i]     - base;
        const int pe = g_rowptr[i + 1] - base;
        const int ps = (pe < CAP1) ? pe : CAP1;
        float a0 = 0.0f, a1 = 0.0f, a2 = 0.0f, a3 = 0.0f;
        float b0 = 0.0f, b1 = 0.0f, b2 = 0.0f, b3 = 0.0f;
        for (; p + 4 <= ps; p += 4) {
            const int   c0 = scol[p    ], c1 = scol[p + 1];
            const int   c2 = scol[p + 2], c3 = scol[p + 3];
            const float v0 = sval[p    ], v1 = sval[p + 1];
            const float v2 = sval[p + 2], v3 = sval[p + 3];
            a0 = fmaf(v0, __ldg(&inp [c0 * HH + m]), a0);
            b0 = fmaf(v0, __ldg(&h_in[c0 * HH + m]), b0);
            a1 = fmaf(v1, __ldg(&inp [c1 * HH + m]), a1);
            b1 = fmaf(v1, __ldg(&h_in[c1 * HH + m]), b1);
            a2 = fmaf(v2, __ldg(&inp [c2 * HH + m]), a2);
            b2 = fmaf(v2, __ldg(&h_in[c2 * HH + m]), b2);
            a3 = fmaf(v3, __ldg(&inp [c3 * HH + m]), a3);
            b3 = fmaf(v3, __ldg(&h_in[c3 * HH + m]), b3);
        }
        for (; p < ps; ++p) {
            const int   c = scol[p];
            const float v = sval[p];
            a0 = fmaf(v, __ldg(&inp [c * HH + m]), a0);
            b0 = fmaf(v, __ldg(&h_in[c * HH + m]), b0);
        }
        for (; p < pe; ++p) {  // overflow fallback (exact; normally never runs)
            const int   c = g_col[base + p];
            const float v = g_val[base + p];
            a0 = fmaf(v, __ldg(&inp [c * HH + m]), a0);
            b0 = fmaf(v, __ldg(&h_in[c * HH + m]), b0);
        }
        sAi[r * 64 + m] = (a0 + a1) + (a2 + a3);
        sAh[r * 64 + m] = (b0 + b1) + (b2 + b3);
    }
    __syncthreads();

    // GEMM phase: thread owns gate-column kk2 = tid for all 16 rows; 4 matrices.
    const int kk2 = tid;
    float acc[RT1];
    {
        const float bb = __ldg(&bgi[kk2]) + __ldg(&bgh[kk2]) + __ldg(&bli[kk2]) + __ldg(&blh[kk2]);
#pragma unroll
        for (int r = 0; r < RT1; ++r) acc[r] = bb;
    }

#pragma unroll 1
    for (int mm = 0; mm < HH; mm += 4) {
        const float w0 = __ldg(&Wgi[(mm + 0) * G4 + kk2]);
        const float w1 = __ldg(&Wgi[(mm + 1) * G4 + kk2]);
        const float w2 = __ldg(&Wgi[(mm + 2) * G4 + kk2]);
        const float w3 = __ldg(&Wgi[(mm + 3) * G4 + kk2]);
        const float u0 = __ldg(&Wgh[(mm + 0) * G4 + kk2]);
        const float u1 = __ldg(&Wgh[(mm + 1) * G4 + kk2]);
        const float u2 = __ldg(&Wgh[(mm + 2) * G4 + kk2]);
        const float u3 = __ldg(&Wgh[(mm + 3) * G4 + kk2]);
#pragma unroll
        for (int r = 0; r < RT1; ++r) {
            const float4 va = *(const float4*)&sAi[r * 64 + mm];
            const float4 vh = *(const float4*)&sAh[r * 64 + mm];
            acc[r] = fmaf(va.x, w0, acc[r]); acc[r] = fmaf(va.y, w1, acc[r]);
            acc[r] = fmaf(va.z, w2, acc[r]); acc[r] = fmaf(va.w, w3, acc[r]);
            acc[r] = fmaf(vh.x, u0, acc[r]); acc[r] = fmaf(vh.y, u1, acc[r]);
            acc[r] = fmaf(vh.z, u2, acc[r]); acc[r] = fmaf(vh.w, u3, acc[r]);
        }
    }
#pragma unroll 1
    for (int mm = 0; mm < HH; mm += 4) {
        const float w0 = __ldg(&Wli[(mm + 0) * G4 + kk2]);
        const float w1 = __ldg(&Wli[(mm + 1) * G4 + kk2]);
        const float w2 = __ldg(&Wli[(mm + 2) * G4 + kk2]);
        const float w3 = __ldg(&Wli[(mm + 3) * G4 + kk2]);
        const float u0 = __ldg(&Wlh[(mm + 0) * G4 + kk2]);
        const float u1 = __ldg(&Wlh[(mm + 1) * G4 + kk2]);
        const float u2 = __ldg(&Wlh[(mm + 2) * G4 + kk2]);
        const float u3 = __ldg(&Wlh[(mm + 3) * G4 + kk2]);
#pragma unroll
        for (int r = 0; r < RT1; ++r) {
            const float4 vi = *(const float4*)&sI[r * 64 + mm];
            const float4 vh = *(const float4*)&sH[r * 64 + mm];
            acc[r] = fmaf(vi.x, w0, acc[r]); acc[r] = fmaf(vi.y, w1, acc[r]);
            acc[r] = fmaf(vi.z, w2, acc[r]); acc[r] = fmaf(vi.w, w3, acc[r]);
            acc[r] = fmaf(vh.x, u0, acc[r]); acc[r] = fmaf(vh.y, u1, acc[r]);
            acc[r] = fmaf(vh.z, u2, acc[r]); acc[r] = fmaf(vh.w, u3, acc[r]);
        }
    }

    // Elementwise phase: 2 chunks of 8 rows
#pragma unroll
    for (int r0 = 0; r0 < RT1; r0 += 8) {
        __syncthreads();
#pragma unroll
        for (int rr = 0; rr < 8; ++rr)
            scomb[rr * 256 + kk2] = acc[r0 + rr];
        __syncthreads();
        const int rw = tid >> 5;
        const int hh = (tid & 31) * 2;
        const int i  = row0 + r0 + rw;
        const float2 ci = *(const float2*)&scomb[rw * 256 + hh      ];
        const float2 cf = *(const float2*)&scomb[rw * 256 + hh +  64];
        const float2 co = *(const float2*)&scomb[rw * 256 + hh + 128];
        const float2 cg = *(const float2*)&scomb[rw * 256 + hh + 192];
        const float2 cold = *(const float2*)&c_in[i * HH + hh];
        float2 cn, hn;
        cn.x = sigm(cf.x) * cold.x + sigm(ci.x) * tanhf(cg.x);
        cn.y = sigm(cf.y) * cold.y + sigm(ci.y) * tanhf(cg.y);
        hn.x = sigm(co.x) * tanhf(cn.x);
        hn.y = sigm(co.y) * tanhf(cn.y);
        *(float2*)&c_out[i * HH + hh] = cn;
        *(float2*)&h_out[i * HH + hh] = hn;
    }
}

// ---------------- kernels --------------------------------------------------------

// Standalone cell0 (first step only)
__global__ void __launch_bounds__(256, 3) cell0_kernel(
    int t, int rd,
    const float* __restrict__ Wgi, const float* __restrict__ Wgh,
    const float* __restrict__ Wli, const float* __restrict__ Wlh,
    const float* __restrict__ bgi, const float* __restrict__ bgh,
    const float* __restrict__ bli, const float* __restrict__ blh)
{
    __shared__ __align__(16) float sbuf[SBUF_F];
    cell0_body(sbuf, blockIdx.x * RT0, t,
               g_h0[rd], g_c0[rd], g_h0[rd ^ 1], g_c0[rd ^ 1],
               Wgi, Wgh, Wli, Wlh, bgi, bgh, bli, blh);
}

// Standalone cell1 (last step only)
__global__ void __launch_bounds__(256, 3) cell1_kernel(
    int rd,
    const float* __restrict__ Wgi, const float* __restrict__ Wgh,
    const float* __restrict__ Wli, const float* __restrict__ Wlh,
    const float* __restrict__ bgi, const float* __restrict__ bgh,
    const float* __restrict__ bli, const float* __restrict__ blh)
{
    __shared__ __align__(16) float sbuf[SBUF_F];
    cell1_body(sbuf, blockIdx.x * RT1,
               g_h0[rd ^ 1], g_h1[rd], g_c1[rd], g_h1[rd ^ 1], g_c1[rd ^ 1],
               Wgi, Wgh, Wli, Wlh, bgi, bgh, bli, blh);
}

// Fused: cell1(tnext-1) runs concurrently with cell0(tnext).
__global__ void __launch_bounds__(256, 3) step_kernel(
    int tnext,
    const float* __restrict__ Wgi0, const float* __restrict__ Wgh0,
    const float* __restrict__ Wli0, const float* __restrict__ Wlh0,
    const float* __restrict__ bgi0, const float* __restrict__ bgh0,
    const float* __restrict__ bli0, const float* __restrict__ blh0,
    const float* __restrict__ Wgi1, const float* __restrict__ Wgh1,
    const float* __restrict__ Wli1, const float* __restrict__ Wlh1,
    const float* __restrict__ bgi1, const float* __restrict__ bgh1,
    const float* __restrict__ bli1, const float* __restrict__ blh1)
{
    __shared__ __align__(16) float sbuf[SBUF_F];
    const int rd0 = tnext & 1;         // cell0 parity at step tnext
    const int rd1 = rd0 ^ 1;           // cell1 parity at step tnext-1
    if (blockIdx.x < NB0) {
        cell0_body(sbuf, blockIdx.x * RT0, tnext,
                   g_h0[rd0], g_c0[rd0], g_h0[rd0 ^ 1], g_c0[rd0 ^ 1],
                   Wgi0, Wgh0, Wli0, Wlh0, bgi0, bgh0, bli0, blh0);
    } else {
        cell1_body(sbuf, (blockIdx.x - NB0) * RT1,
                   g_h0[rd0],                  // inp = h0(tnext-1)
                   g_h1[rd1], g_c1[rd1], g_h1[rd1 ^ 1], g_c1[rd1 ^ 1],
                   Wgi1, Wgh1, Wli1, Wlh1, bgi1, bgh1, bli1, blh1);
    }
}

// Final projection: out[i,p] = h1[i,:] @ outW[:,p] + outb[p]
__global__ void out_kernel(const float* __restrict__ outW,
                           const float* __restrict__ outb,
                           float* __restrict__ out)
{
    const int idx = blockIdx.x * blockDim.x + threadIdx.x;
    if (idx >= NN * PP) return;
    const int i = idx / PP;
    const int p = idx % PP;
    const float* h = &g_h1[0][i * HH];   // parity 0 after 48 steps
    float acc = __ldg(&outb[p]);
#pragma unroll
    for (int mm = 0; mm < HH; ++mm)
        acc = fmaf(h[mm], __ldg(&outW[mm * PP + p]), acc);
    out[idx] = acc;
}

// ---------------- launch --------------------------------------------------------
extern "C" void kernel_launch(void* const* d_in, const int* in_sizes, int n_in,
                              void* d_out, int out_size) {
    const float* x     = (const float*)d_in[0];
    const float* adj   = (const float*)d_in[1];
    const float* gcWi0 = (const float*)d_in[2];  const float* gcbi0 = (const float*)d_in[3];
    const float* gcWh0 = (const float*)d_in[4];  const float* gcbh0 = (const float*)d_in[5];
    const float* liWi0 = (const float*)d_in[6];  const float* libi0 = (const float*)d_in[7];
    const float* liWh0 = (const float*)d_in[8];  const float* libh0 = (const float*)d_in[9];
    const float* gcWi1 = (const float*)d_in[10]; const float* gcbi1 = (const float*)d_in[11];
    const float* gcWh1 = (const float*)d_in[12]; const float* gcbh1 = (const float*)d_in[13];
    const float* liWi1 = (const float*)d_in[14]; const float* libi1 = (const float*)d_in[15];
    const float* liWh1 = (const float*)d_in[16]; const float* libh1 = (const float*)d_in[17];
    const float* outW  = (const float*)d_in[18]; const float* outb  = (const float*)d_in[19];
    float* out = (float*)d_out;

    // Preprocessing (captured in the graph; deterministic)
    degree_kernel<<<NN, 128>>>(adj);
    scan_kernel<<<1, 1024>>>();
    fill_kernel<<<(NN * 32 + 255) / 256, 256>>>(adj);
    xT_kernel<<<(NN * 96 + 255) / 256, 256>>>(x);
    ax_kernel<<<NN, 96>>>();
    zero_kernel<<<(NN * HH + 255) / 256, 256>>>();

    // Step 0: cell0 alone (reads zeroed h0[0], writes h0[1])
    cell0_kernel<<<NB0, 256>>>(0, 0,
        gcWi0, gcWh0, liWi0, liWh0, gcbi0, gcbh0, libi0, libh0);

    // Steps: fused cell1(t-1) || cell0(t) for t = 1..47
    for (int tnext = 1; tnext < TT; ++tnext) {
        step_kernel<<<NB0 + NB1, 256>>>(tnext,
            gcWi0, gcWh0, liWi0, liWh0, gcbi0, gcbh0, libi0, libh0,
            gcWi1, gcWh1, liWi1, liWh1, gcbi1, gcbh1, libi1, libh1);
    }

    // Last: cell1 for step 47 (rd = 47 & 1 = 1)
    cell1_kernel<<<NB1, 256>>>(1,
        gcWi1, gcWh1, liWi1, liWh1, gcbi1, gcbh1, libi1, libh1);

    out_kernel<<<(NN * PP + 255) / 256, 256>>>(outW, outb, out);
}

// round 11
// speedup vs baseline: 1.8832x; 1.0683x over previous
#include <cuda_runtime.h>
#include <cuda_bf16.h>
#include <math.h>

// Problem constants
#define NN    4096          // graph nodes
#define TT    48            // timesteps
#define HH    64            // hidden
#define INW   2             // input width
#define PP    12            // output width
#define G4    256           // 4*H
#define RT0   32            // rows per block, cell0
#define RT1   16            // rows per block, cell1
#define NB0   (NN / RT0)    // 128 blocks for cell0
#define NB1   (NN / RT1)    // 256 blocks for cell1
#define CAP0  2048          // staged nnz cap, cell0 (expected ~1344/block)
#define CAP1  1024          // staged nnz cap, cell1 (expected ~672/block)

#define NNZ_MAX (1 << 19)

// ---------------- device scratch -------------------------------------------------
__device__ int   g_rowptr[NN + 1];
__device__ int   g_rowcnt[NN];
__device__ int   g_col[NNZ_MAX];
__device__ float g_val[NNZ_MAX];
__device__ float g_dinv[NN];
__device__ float g_xT[NN * 96];   // x transposed: [node][t*2+c]
__device__ float g_AX[NN * 96];   // A @ x, same layout
__device__ float g_h0[2][NN * HH];
__device__ float g_c0[2][NN * HH];
__device__ float g_h1[2][NN * HH];
__device__ float g_c1[2][NN * HH];

// Fast gates: MUFU-based. Inf-safe: __expf(big)=inf -> __fdividef(2,inf)=0.
__device__ __forceinline__ float fsigm(float x) {
    return __fdividef(1.0f, 1.0f + __expf(-x));
}
__device__ __forceinline__ float ftanh(float x) {
    return 1.0f - __fdividef(2.0f, __expf(2.0f * x) + 1.0f);
}

// ---------------- preprocessing -------------------------------------------------
__global__ void degree_kernel(const float* __restrict__ adj) {
    const int i = blockIdx.x;
    const int tid = threadIdx.x;
    const float* row = adj + (size_t)i * NN;
    float d = 0.0f;
    int cnt = 0;
    for (int j = tid; j < NN; j += blockDim.x) {
        const float a = __ldg(&row[j]);
        d += a;
        cnt += (a != 0.0f && j != i) ? 1 : 0;
    }
    __shared__ float sd[128];
    __shared__ int   sc[128];
    sd[tid] = d; sc[tid] = cnt;
    __syncthreads();
    for (int off = 64; off > 0; off >>= 1) {
        if (tid < off) { sd[tid] += sd[tid + off]; sc[tid] += sc[tid + off]; }
        __syncthreads();
    }
    if (tid == 0) {
        const float dd = sd[0] + 1.0f;
        g_dinv[i]   = 1.0f / sqrtf(dd);
        g_rowcnt[i] = sc[0] + 1;
    }
}

__global__ void scan_kernel() {
    __shared__ int s[1024];
    const int tid = threadIdx.x;
    int c[4];
    int sum = 0;
#pragma unroll
    for (int u = 0; u < 4; ++u) { c[u] = g_rowcnt[tid * 4 + u]; sum += c[u]; }
    s[tid] = sum;
    __syncthreads();
    for (int off = 1; off < 1024; off <<= 1) {
        const int v = (tid >= off) ? s[tid - off] : 0;
        __syncthreads();
        s[tid] += v;
        __syncthreads();
    }
    int excl = s[tid] - sum;
#pragma unroll
    for (int u = 0; u < 4; ++u) { g_rowptr[tid * 4 + u] = excl; excl += c[u]; }
    if (tid == 1023) g_rowptr[NN] = s[1023];
}

__global__ void fill_kernel(const float* __restrict__ adj) {
    const int w = (blockIdx.x * blockDim.x + threadIdx.x) >> 5;
    const int lane = threadIdx.x & 31;
    if (w >= NN) return;
    const int i = w;
    const float* row = adj + (size_t)i * NN;
    const float di = g_dinv[i];
    int base = g_rowptr[i];
    for (int j0 = 0; j0 < NN; j0 += 32) {
        const int j = j0 + lane;
        const float a = __ldg(&row[j]);
        const bool pred = (a != 0.0f) || (j == i);
        const unsigned mask = __ballot_sync(0xffffffffu, pred);
        if (pred) {
            const int idx = base + __popc(mask & ((1u << lane) - 1u));
            if (idx < NNZ_MAX) {
                g_col[idx] = j;
                const float v = a + ((j == i) ? 1.0f : 0.0f);
                g_val[idx] = di * g_dinv[j] * v;
            }
        }
        base += __popc(mask);
    }
}

__global__ void xT_kernel(const float* __restrict__ x) {
    const int idx = blockIdx.x * blockDim.x + threadIdx.x;
    if (idx >= NN * 96) return;
    const int n = idx / 96;
    const int k = idx % 96;
    const int t = k >> 1;
    const int c = k & 1;
    g_xT[idx] = __ldg(&x[t * (NN * INW) + n * INW + c]);
}

__global__ void ax_kernel() {
    const int i = blockIdx.x;
    const int k = threadIdx.x;  // 0..95
    const int p0 = g_rowptr[i], p1 = g_rowptr[i + 1];
    float acc = 0.0f;
    for (int p = p0; p < p1; ++p)
        acc = fmaf(g_val[p], g_xT[g_col[p] * 96 + k], acc);
    g_AX[i * 96 + k] = acc;
}

__global__ void zero_kernel() {
    const int idx = blockIdx.x * blockDim.x + threadIdx.x;
    if (idx < NN * HH) {
        g_h0[0][idx] = 0.0f; g_c0[0][idx] = 0.0f;
        g_h1[0][idx] = 0.0f; g_c1[0][idx] = 0.0f;
    }
}

// ---------------- cell bodies ----------------------------------------------------
// Shared buffer union (floats), 16B aligned; SBUF_F = 8320 (33.3 KB):
//   cell0 phase A/B: sAh[32][64]@0, sH[32][64]@2048, sXA[32][2]@4096, sXI[32][2]@4160,
//                    scol[2048](int)@4224, sval[2048]@6272
//   cell0 phase C  : comb[32][256]@0 (overlays everything; GEMM inputs dead)
//   cell1 phase A/B: sAi[16][64]@0, sAh@1024, sI@2048, sH@3072,
//                    scol[1024](int)@4096, sval[1024]@5120
//   cell1 phase C  : comb[16][256]@0
#define SBUF_F 8320

__device__ __forceinline__ void cell0_body(
    float* __restrict__ sbuf, int row0, int t,
    const float* __restrict__ h_in, const float* __restrict__ c_in,
    float* __restrict__ h_out, float* __restrict__ c_out,
    const float* __restrict__ Wgi, const float* __restrict__ Wgh,
    const float* __restrict__ Wli, const float* __restrict__ Wlh,
    const float* __restrict__ bgi, const float* __restrict__ bgh,
    const float* __restrict__ bli, const float* __restrict__ blh)
{
    const int tid = threadIdx.x;
    const int m   = tid & 63;
    const int rg  = tid >> 6;

    float* sAh  = sbuf;           // [32][64]
    float* sH   = sbuf + 2048;    // [32][64]
    float* sXA  = sbuf + 4096;    // [32][2]
    float* sXI  = sbuf + 4160;    // [32][2]
    int*   scol = (int*)(sbuf + 4224);   // [CAP0]
    float* sval = sbuf + 6272;           // [CAP0]
    float* scomb = sbuf;                 // [32][256], overlays all after GEMM

    // Stage this block's CSR segment into smem (coalesced, high MLP)
    const int base = g_rowptr[row0];
    const int tot  = g_rowptr[row0 + RT0] - base;
    const int nst  = (tot < CAP0) ? tot : CAP0;
    for (int q = tid; q < nst; q += 256) {
        scol[q] = g_col[base + q];
        sval[q] = g_val[base + q];
    }
    __syncthreads();

    // Gather phase: deep-unrolled independent gathers (MLP ~8)
    for (int r = rg; r < RT0; r += 4) {
        const int i = row0 + r;
        sH[r * 64 + m] = __ldg(&h_in[i * HH + m]);
        int       p  = g_rowptr[i]     - base;
        const int pe = g_rowptr[i + 1] - base;
        const int ps = (pe < CAP0) ? pe : CAP0;
        float a0 = 0.0f, a1 = 0.0f, a2 = 0.0f, a3 = 0.0f;
        for (; p + 8 <= ps; p += 8) {
            const int   c0 = scol[p    ], c1 = scol[p + 1];
            const int   c2 = scol[p + 2], c3 = scol[p + 3];
            const int   c4 = scol[p + 4], c5 = scol[p + 5];
            const int   c6 = scol[p + 6], c7 = scol[p + 7];
            const float v0 = sval[p    ], v1 = sval[p + 1];
            const float v2 = sval[p + 2], v3 = sval[p + 3];
            const float v4 = sval[p + 4], v5 = sval[p + 5];
            const float v6 = sval[p + 6], v7 = sval[p + 7];
            a0 = fmaf(v0, __ldg(&h_in[c0 * HH + m]), a0);
            a1 = fmaf(v1, __ldg(&h_in[c1 * HH + m]), a1);
            a2 = fmaf(v2, __ldg(&h_in[c2 * HH + m]), a2);
            a3 = fmaf(v3, __ldg(&h_in[c3 * HH + m]), a3);
            a0 = fmaf(v4, __ldg(&h_in[c4 * HH + m]), a0);
            a1 = fmaf(v5, __ldg(&h_in[c5 * HH + m]), a1);
            a2 = fmaf(v6, __ldg(&h_in[c6 * HH + m]), a2);
            a3 = fmaf(v7, __ldg(&h_in[c7 * HH + m]), a3);
        }
        for (; p < ps; ++p)
            a0 = fmaf(sval[p], __ldg(&h_in[scol[p] * HH + m]), a0);
        for (; p < pe; ++p)   // overflow fallback (exact; normally never runs)
            a0 = fmaf(g_val[base + p], __ldg(&h_in[g_col[base + p] * HH + m]), a0);
        sAh[r * 64 + m] = (a0 + a1) + (a2 + a3);
        if (m < 2) {
            sXA[r * 2 + m] = g_AX[i * 96 + 2 * t + m];
            sXI[r * 2 + m] = g_xT[i * 96 + 2 * t + m];
        }
    }
    __syncthreads();

    // GEMM phase: thread owns gate-column kk2 = tid for ALL 32 rows.
    const int kk2 = tid;
    float acc[RT0];
    {
        const float bb = __ldg(&bgi[kk2]) + __ldg(&bgh[kk2]) + __ldg(&bli[kk2]) + __ldg(&blh[kk2]);
#pragma unroll
        for (int r = 0; r < RT0; ++r) acc[r] = bb;
    }

#pragma unroll 1
    for (int mm = 0; mm < HH; mm += 4) {
        const float w0 = __ldg(&Wgh[(mm + 0) * G4 + kk2]);
        const float w1 = __ldg(&Wgh[(mm + 1) * G4 + kk2]);
        const float w2 = __ldg(&Wgh[(mm + 2) * G4 + kk2]);
        const float w3 = __ldg(&Wgh[(mm + 3) * G4 + kk2]);
        const float u0 = __ldg(&Wlh[(mm + 0) * G4 + kk2]);
        const float u1 = __ldg(&Wlh[(mm + 1) * G4 + kk2]);
        const float u2 = __ldg(&Wlh[(mm + 2) * G4 + kk2]);
        const float u3 = __ldg(&Wlh[(mm + 3) * G4 + kk2]);
#pragma unroll
        for (int r = 0; r < RT0; ++r) {
            const float4 va = *(const float4*)&sAh[r * 64 + mm];
            const float4 vh = *(const float4*)&sH [r * 64 + mm];
            acc[r] = fmaf(va.x, w0, acc[r]); acc[r] = fmaf(va.y, w1, acc[r]);
            acc[r] = fmaf(va.z, w2, acc[r]); acc[r] = fmaf(va.w, w3, acc[r]);
            acc[r] = fmaf(vh.x, u0, acc[r]); acc[r] = fmaf(vh.y, u1, acc[r]);
            acc[r] = fmaf(vh.z, u2, acc[r]); acc[r] = fmaf(vh.w, u3, acc[r]);
        }
    }
    {   // input terms (K = 2 each)
        const float wa0 = __ldg(&Wgi[0 * G4 + kk2]);
        const float wa1 = __ldg(&Wgi[1 * G4 + kk2]);
        const float wi0 = __ldg(&Wli[0 * G4 + kk2]);
        const float wi1 = __ldg(&Wli[1 * G4 + kk2]);
#pragma unroll
        for (int r = 0; r < RT0; ++r) {
            const float2 xa = *(const float2*)&sXA[r * 2];
            const float2 xi = *(const float2*)&sXI[r * 2];
            acc[r] = fmaf(xa.x, wa0, acc[r]); acc[r] = fmaf(xa.y, wa1, acc[r]);
            acc[r] = fmaf(xi.x, wi0, acc[r]); acc[r] = fmaf(xi.y, wi1, acc[r]);
        }
    }

    // Elementwise phase: full comb overlay, 2 syncs total.
    __syncthreads();   // all GEMM shared reads complete; sbuf reusable
#pragma unroll
    for (int r = 0; r < RT0; ++r)
        scomb[r * 256 + kk2] = acc[r];
    __syncthreads();
    {
        const int rw = tid >> 5;             // warp w -> row offset
        const int hh = (tid & 31) * 2;       // 2 hidden units per lane
#pragma unroll
        for (int pass = 0; pass < RT0 / 8; ++pass) {
            const int row = pass * 8 + rw;
            const int i   = row0 + row;
            const float2 ci = *(const float2*)&scomb[row * 256 + hh      ];
            const float2 cf = *(const float2*)&scomb[row * 256 + hh +  64];
            const float2 co = *(const float2*)&scomb[row * 256 + hh + 128];
            const float2 cg = *(const float2*)&scomb[row * 256 + hh + 192];
            const float2 cold = *(const float2*)&c_in[i * HH + hh];
            float2 cn, hn;
            cn.x = fsigm(cf.x) * cold.x + fsigm(ci.x) * ftanh(cg.x);
            cn.y = fsigm(cf.y) * cold.y + fsigm(ci.y) * ftanh(cg.y);
            hn.x = fsigm(co.x) * ftanh(cn.x);
            hn.y = fsigm(co.y) * ftanh(cn.y);
            *(float2*)&c_out[i * HH + hh] = cn;
            *(float2*)&h_out[i * HH + hh] = hn;
        }
    }
}

__device__ __forceinline__ void cell1_body(
    float* __restrict__ sbuf, int row0,
    const float* __restrict__ inp,  const float* __restrict__ h_in,
    const float* __restrict__ c_in,
    float* __restrict__ h_out, float* __restrict__ c_out,
    const float* __restrict__ Wgi, const float* __restrict__ Wgh,
    const float* __restrict__ Wli, const float* __restrict__ Wlh,
    const float* __restrict__ bgi, const float* __restrict__ bgh,
    const float* __restrict__ bli, const float* __restrict__ blh)
{
    const int tid = threadIdx.x;
    const int m   = tid & 63;
    const int rg  = tid >> 6;

    float* sAi  = sbuf;           // [16][64]
    float* sAh  = sbuf + 1024;
    float* sI   = sbuf + 2048;
    float* sH   = sbuf + 3072;
    int*   scol = (int*)(sbuf + 4096);   // [CAP1]
    float* sval = sbuf + 5120;           // [CAP1]
    float* scomb = sbuf;                 // [16][256], overlays all after GEMM

    // Stage this block's CSR segment into smem
    const int base = g_rowptr[row0];
    const int tot  = g_rowptr[row0 + RT1] - base;
    const int nst  = (tot < CAP1) ? tot : CAP1;
    for (int q = tid; q < nst; q += 256) {
        scol[q] = g_col[base + q];
        sval[q] = g_val[base + q];
    }
    __syncthreads();

    for (int r = rg; r < RT1; r += 4) {
        const int i = row0 + r;
        sI[r * 64 + m] = __ldg(&inp [i * HH + m]);
        sH[r * 64 + m] = __ldg(&h_in[i * HH + m]);
        int       p  = g_rowptr[i]     - base;
        const int pe = g_rowptr[i + 1] - base;
        const int ps = (pe < CAP1) ? pe : CAP1;
        float a0 = 0.0f, a1 = 0.0f, a2 = 0.0f, a3 = 0.0f;
        float b0 = 0.0f, b1 = 0.0f, b2 = 0.0f, b3 = 0.0f;
        for (; p + 4 <= ps; p += 4) {
            const int   c0 = scol[p    ], c1 = scol[p + 1];
            const int   c2 = scol[p + 2], c3 = scol[p + 3];
            const float v0 = sval[p    ], v1 = sval[p + 1];
            const float v2 = sval[p + 2], v3 = sval[p + 3];
            a0 = fmaf(v0, __ldg(&inp [c0 * HH + m]), a0);
            b0 = fmaf(v0, __ldg(&h_in[c0 * HH + m]), b0);
            a1 = fmaf(v1, __ldg(&inp [c1 * HH + m]), a1);
            b1 = fmaf(v1, __ldg(&h_in[c1 * HH + m]), b1);
            a2 = fmaf(v2, __ldg(&inp [c2 * HH + m]), a2);
            b2 = fmaf(v2, __ldg(&h_in[c2 * HH + m]), b2);
            a3 = fmaf(v3, __ldg(&inp [c3 * HH + m]), a3);
            b3 = fmaf(v3, __ldg(&h_in[c3 * HH + m]), b3);
        }
        for (; p < ps; ++p) {
            const int   c = scol[p];
            const float v = sval[p];
            a0 = fmaf(v, __ldg(&inp [c * HH + m]), a0);
            b0 = fmaf(v, __ldg(&h_in[c * HH + m]), b0);
        }
        for (; p < pe; ++p) {  // overflow fallback (exact; normally never runs)
            const int   c = g_col[base + p];
            const float v = g_val[base + p];
            a0 = fmaf(v, __ldg(&inp [c * HH + m]), a0);
            b0 = fmaf(v, __ldg(&h_in[c * HH + m]), b0);
        }
        sAi[r * 64 + m] = (a0 + a1) + (a2 + a3);
        sAh[r * 64 + m] = (b0 + b1) + (b2 + b3);
    }
    __syncthreads();

    // GEMM phase: thread owns gate-column kk2 = tid for all 16 rows; 4 matrices.
    const int kk2 = tid;
    float acc[RT1];
    {
        const float bb = __ldg(&bgi[kk2]) + __ldg(&bgh[kk2]) + __ldg(&bli[kk2]) + __ldg(&blh[kk2]);
#pragma unroll
        for (int r = 0; r < RT1; ++r) acc[r] = bb;
    }

#pragma unroll 1
    for (int mm = 0; mm < HH; mm += 4) {
        const float w0 = __ldg(&Wgi[(mm + 0) * G4 + kk2]);
        const float w1 = __ldg(&Wgi[(mm + 1) * G4 + kk2]);
        const float w2 = __ldg(&Wgi[(mm + 2) * G4 + kk2]);
        const float w3 = __ldg(&Wgi[(mm + 3) * G4 + kk2]);
        const float u0 = __ldg(&Wgh[(mm + 0) * G4 + kk2]);
        const float u1 = __ldg(&Wgh[(mm + 1) * G4 + kk2]);
        const float u2 = __ldg(&Wgh[(mm + 2) * G4 + kk2]);
        const float u3 = __ldg(&Wgh[(mm + 3) * G4 + kk2]);
#pragma unroll
        for (int r = 0; r < RT1; ++r) {
            const float4 va = *(const float4*)&sAi[r * 64 + mm];
            const float4 vh = *(const float4*)&sAh[r * 64 + mm];
            acc[r] = fmaf(va.x, w0, acc[r]); acc[r] = fmaf(va.y, w1, acc[r]);
            acc[r] = fmaf(va.z, w2, acc[r]); acc[r] = fmaf(va.w, w3, acc[r]);
            acc[r] = fmaf(vh.x, u0, acc[r]); acc[r] = fmaf(vh.y, u1, acc[r]);
            acc[r] = fmaf(vh.z, u2, acc[r]); acc[r] = fmaf(vh.w, u3, acc[r]);
        }
    }
#pragma unroll 1
    for (int mm = 0; mm < HH; mm += 4) {
        const float w0 = __ldg(&Wli[(mm + 0) * G4 + kk2]);
        const float w1 = __ldg(&Wli[(mm + 1) * G4 + kk2]);
        const float w2 = __ldg(&Wli[(mm + 2) * G4 + kk2]);
        const float w3 = __ldg(&Wli[(mm + 3) * G4 + kk2]);
        const float u0 = __ldg(&Wlh[(mm + 0) * G4 + kk2]);
        const float u1 = __ldg(&Wlh[(mm + 1) * G4 + kk2]);
        const float u2 = __ldg(&Wlh[(mm + 2) * G4 + kk2]);
        const float u3 = __ldg(&Wlh[(mm + 3) * G4 + kk2]);
#pragma unroll
        for (int r = 0; r < RT1; ++r) {
            const float4 vi = *(const float4*)&sI[r * 64 + mm];
            const float4 vh = *(const float4*)&sH[r * 64 + mm];
            acc[r] = fmaf(vi.x, w0, acc[r]); acc[r] = fmaf(vi.y, w1, acc[r]);
            acc[r] = fmaf(vi.z, w2, acc[r]); acc[r] = fmaf(vi.w, w3, acc[r]);
            acc[r] = fmaf(vh.x, u0, acc[r]); acc[r] = fmaf(vh.y, u1, acc[r]);
            acc[r] = fmaf(vh.z, u2, acc[r]); acc[r] = fmaf(vh.w, u3, acc[r]);
        }
    }

    // Elementwise phase: full comb overlay, 2 syncs total.
    __syncthreads();
#pragma unroll
    for (int r = 0; r < RT1; ++r)
        scomb[r * 256 + kk2] = acc[r];
    __syncthreads();
    {
        const int rw = tid >> 5;
        const int hh = (tid & 31) * 2;
#pragma unroll
        for (int pass = 0; pass < RT1 / 8; ++pass) {
            const int row = pass * 8 + rw;
            const int i   = row0 + row;
            const float2 ci = *(const float2*)&scomb[row * 256 + hh      ];
            const float2 cf = *(const float2*)&scomb[row * 256 + hh +  64];
            const float2 co = *(const float2*)&scomb[row * 256 + hh + 128];
            const float2 cg = *(const float2*)&scomb[row * 256 + hh + 192];
            const float2 cold = *(const float2*)&c_in[i * HH + hh];
            float2 cn, hn;
            cn.x = fsigm(cf.x) * cold.x + fsigm(ci.x) * ftanh(cg.x);
            cn.y = fsigm(cf.y) * cold.y + fsigm(ci.y) * ftanh(cg.y);
            hn.x = fsigm(co.x) * ftanh(cn.x);
            hn.y = fsigm(co.y) * ftanh(cn.y);
            *(float2*)&c_out[i * HH + hh] = cn;
            *(float2*)&h_out[i * HH + hh] = hn;
        }
    }
}

// ---------------- kernels --------------------------------------------------------

// Standalone cell0 (first step only)
__global__ void __launch_bounds__(256, 3) cell0_kernel(
    int t, int rd,
    const float* __restrict__ Wgi, const float* __restrict__ Wgh,
    const float* __restrict__ Wli, const float* __restrict__ Wlh,
    const float* __restrict__ bgi, const float* __restrict__ bgh,
    const float* __restrict__ bli, const float* __restrict__ blh)
{
    __shared__ __align__(16) float sbuf[SBUF_F];
    cell0_body(sbuf, blockIdx.x * RT0, t,
               g_h0[rd], g_c0[rd], g_h0[rd ^ 1], g_c0[rd ^ 1],
               Wgi, Wgh, Wli, Wlh, bgi, bgh, bli, blh);
}

// Standalone cell1 (last step only)
__global__ void __launch_bounds__(256, 3) cell1_kernel(
    int rd,
    const float* __restrict__ Wgi, const float* __restrict__ Wgh,
    const float* __restrict__ Wli, const float* __restrict__ Wlh,
    const float* __restrict__ bgi, const float* __restrict__ bgh,
    const float* __restrict__ bli, const float* __restrict__ blh)
{
    __shared__ __align__(16) float sbuf[SBUF_F];
    cell1_body(sbuf, blockIdx.x * RT1,
               g_h0[rd ^ 1], g_h1[rd], g_c1[rd], g_h1[rd ^ 1], g_c1[rd ^ 1],
               Wgi, Wgh, Wli, Wlh, bgi, bgh, bli, blh);
}

// Fused: cell1(tnext-1) runs concurrently with cell0(tnext).
__global__ void __launch_bounds__(256, 3) step_kernel(
    int tnext,
    const float* __restrict__ Wgi0, const float* __restrict__ Wgh0,
    const float* __restrict__ Wli0, const float* __restrict__ Wlh0,
    const float* __restrict__ bgi0, const float* __restrict__ bgh0,
    const float* __restrict__ bli0, const float* __restrict__ blh0,
    const float* __restrict__ Wgi1, const float* __restrict__ Wgh1,
    const float* __restrict__ Wli1, const float* __restrict__ Wlh1,
    const float* __restrict__ bgi1, const float* __restrict__ bgh1,
    const float* __restrict__ bli1, const float* __restrict__ blh1)
{
    __shared__ __align__(16) float sbuf[SBUF_F];
    const int rd0 = tnext & 1;         // cell0 parity at step tnext
    const int rd1 = rd0 ^ 1;           // cell1 parity at step tnext-1
    if (blockIdx.x < NB0) {
        cell0_body(sbuf, blockIdx.x * RT0, tnext,
                   g_h0[rd0], g_c0[rd0], g_h0[rd0 ^ 1], g_c0[rd0 ^ 1],
                   Wgi0, Wgh0, Wli0, Wlh0, bgi0, bgh0, bli0, blh0);
    } else {
        cell1_body(sbuf, (blockIdx.x - NB0) * RT1,
                   g_h0[rd0],                  // inp = h0(tnext-1)
                   g_h1[rd1], g_c1[rd1], g_h1[rd1 ^ 1], g_c1[rd1 ^ 1],
                   Wgi1, Wgh1, Wli1, Wlh1, bgi1, bgh1, bli1, blh1);
    }
}

// Final projection: out[i,p] = h1[i,:] @ outW[:,p] + outb[p]
__global__ void out_kernel(const float* __restrict__ outW,
                           const float* __restrict__ outb,
                           float* __restrict__ out)
{
    const int idx = blockIdx.x * blockDim.x + threadIdx.x;
    if (idx >= NN * PP) return;
    const int i = idx / PP;
    const int p = idx % PP;
    const float* h = &g_h1[0][i * HH];   // parity 0 after 48 steps
    float acc = __ldg(&outb[p]);
#pragma unroll
    for (int mm = 0; mm < HH; ++mm)
        acc = fmaf(h[mm], __ldg(&outW[mm * PP + p]), acc);
    out[idx] = acc;
}

// ---------------- launch --------------------------------------------------------
extern "C" void kernel_launch(void* const* d_in, const int* in_sizes, int n_in,
                              void* d_out, int out_size) {
    const float* x     = (const float*)d_in[0];
    const float* adj   = (const float*)d_in[1];
    const float* gcWi0 = (const float*)d_in[2];  const float* gcbi0 = (const float*)d_in[3];
    const float* gcWh0 = (const float*)d_in[4];  const float* gcbh0 = (const float*)d_in[5];
    const float* liWi0 = (const float*)d_in[6];  const float* libi0 = (const float*)d_in[7];
    const float* liWh0 = (const float*)d_in[8];  const float* libh0 = (const float*)d_in[9];
    const float* gcWi1 = (const float*)d_in[10]; const float* gcbi1 = (const float*)d_in[11];
    const float* gcWh1 = (const float*)d_in[12]; const float* gcbh1 = (const float*)d_in[13];
    const float* liWi1 = (const float*)d_in[14]; const float* libi1 = (const float*)d_in[15];
    const float* liWh1 = (const float*)d_in[16]; const float* libh1 = (const float*)d_in[17];
    const float* outW  = (const float*)d_in[18]; const float* outb  = (const float*)d_in[19];
    float* out = (float*)d_out;

    // Preprocessing (captured in the graph; deterministic)
    degree_kernel<<<NN, 128>>>(adj);
    scan_kernel<<<1, 1024>>>();
    fill_kernel<<<(NN * 32 + 255) / 256, 256>>>(adj);
    xT_kernel<<<(NN * 96 + 255) / 256, 256>>>(x);
    ax_kernel<<<NN, 96>>>();
    zero_kernel<<<(NN * HH + 255) / 256, 256>>>();

    // Step 0: cell0 alone (reads zeroed h0[0], writes h0[1])
    cell0_kernel<<<NB0, 256>>>(0, 0,
        gcWi0, gcWh0, liWi0, liWh0, gcbi0, gcbh0, libi0, libh0);

    // Steps: fused cell1(t-1) || cell0(t) for t = 1..47
    for (int tnext = 1; tnext < TT; ++tnext) {
        step_kernel<<<NB0 + NB1, 256>>>(tnext,
            gcWi0, gcWh0, liWi0, liWh0, gcbi0, gcbh0, libi0, libh0,
            gcWi1, gcWh1, liWi1, liWh1, gcbi1, gcbh1, libi1, libh1);
    }

    // Last: cell1 for step 47 (rd = 47 & 1 = 1)
    cell1_kernel<<<NB1, 256>>>(1,
        gcWi1, gcWh1, liWi1, liWh1, gcbi1, gcbh1, libi1, libh1);

    out_kernel<<<(NN * PP + 255) / 256, 256>>>(outW, outb, out);
}

// round 12
// speedup vs baseline: 1.9111x; 1.0148x over previous
#include <cuda_runtime.h>
#include <cuda_bf16.h>
#include <math.h>

// Problem constants
#define NN    4096          // graph nodes
#define TT    48            // timesteps
#define HH    64            // hidden
#define INW   2             // input width
#define PP    12            // output width
#define G4    256           // 4*H
#define RT0   32            // rows per block, cell0
#define RT1   16            // rows per block, cell1
#define NB0   (NN / RT0)    // 128 blocks for cell0
#define NB1   (NN / RT1)    // 256 blocks for cell1
#define CAP0  2048          // staged nnz cap, cell0 (expected ~1344/block)
#define CAP1  1024          // staged nnz cap, cell1 (expected ~672/block)
#define S0    36            // padded row stride (floats) cell0: 16B-aligned rows, low conflict
#define S1    20            // padded row stride cell1

#define NNZ_MAX (1 << 19)

// ---------------- device scratch -------------------------------------------------
__device__ int   g_rowptr[NN + 1];
__device__ int   g_rowcnt[NN];
__device__ int   g_col[NNZ_MAX];
__device__ float g_val[NNZ_MAX];
__device__ float g_dinv[NN];
__device__ float g_xT[NN * 96];   // x transposed: [node][t*2+c]
__device__ float g_AX[NN * 96];   // A @ x, same layout
__device__ float g_h0[2][NN * HH];
__device__ float g_c0[2][NN * HH];
__device__ float g_h1[2][NN * HH];
__device__ float g_c1[2][NN * HH];

// Fast gates: MUFU-based. Inf-safe: __expf(big)=inf -> __fdividef(2,inf)=0.
__device__ __forceinline__ float fsigm(float x) {
    return __fdividef(1.0f, 1.0f + __expf(-x));
}
__device__ __forceinline__ float ftanh(float x) {
    return 1.0f - __fdividef(2.0f, __expf(2.0f * x) + 1.0f);
}

// Packed f32x2 helpers (Blackwell dual-rate fp32; only reachable via PTX)
#define FMA2(acc, a, b) \
    asm("fma.rn.f32x2 %0, %1, %2, %0;" : "+l"(acc) : "l"(a), "l"(b))
#define PACK2(out, x) \
    asm("mov.b64 %0, {%1, %1};" : "=l"(out) : "f"(x))
#define UNPACK2(lo, hi, in) \
    asm("mov.b64 {%0, %1}, %2;" : "=f"(lo), "=f"(hi) : "l"(in))

// ---------------- preprocessing -------------------------------------------------
__global__ void degree_kernel(const float* __restrict__ adj) {
    const int i = blockIdx.x;
    const int tid = threadIdx.x;
    const float* row = adj + (size_t)i * NN;
    float d = 0.0f;
    int cnt = 0;
    for (int j = tid; j < NN; j += blockDim.x) {
        const float a = __ldg(&row[j]);
        d += a;
        cnt += (a != 0.0f && j != i) ? 1 : 0;
    }
    __shared__ float sd[128];
    __shared__ int   sc[128];
    sd[tid] = d; sc[tid] = cnt;
    __syncthreads();
    for (int off = 64; off > 0; off >>= 1) {
        if (tid < off) { sd[tid] += sd[tid + off]; sc[tid] += sc[tid + off]; }
        __syncthreads();
    }
    if (tid == 0) {
        const float dd = sd[0] + 1.0f;
        g_dinv[i]   = 1.0f / sqrtf(dd);
        g_rowcnt[i] = sc[0] + 1;
    }
}

__global__ void scan_kernel() {
    __shared__ int s[1024];
    const int tid = threadIdx.x;
    int c[4];
    int sum = 0;
#pragma unroll
    for (int u = 0; u < 4; ++u) { c[u] = g_rowcnt[tid * 4 + u]; sum += c[u]; }
    s[tid] = sum;
    __syncthreads();
    for (int off = 1; off < 1024; off <<= 1) {
        const int v = (tid >= off) ? s[tid - off] : 0;
        __syncthreads();
        s[tid] += v;
        __syncthreads();
    }
    int excl = s[tid] - sum;
#pragma unroll
    for (int u = 0; u < 4; ++u) { g_rowptr[tid * 4 + u] = excl; excl += c[u]; }
    if (tid == 1023) g_rowptr[NN] = s[1023];
}

__global__ void fill_kernel(const float* __restrict__ adj) {
    const int w = (blockIdx.x * blockDim.x + threadIdx.x) >> 5;
    const int lane = threadIdx.x & 31;
    if (w >= NN) return;
    const int i = w;
    const float* row = adj + (size_t)i * NN;
    const float di = g_dinv[i];
    int base = g_rowptr[i];
    for (int j0 = 0; j0 < NN; j0 += 32) {
        const int j = j0 + lane;
        const float a = __ldg(&row[j]);
        const bool pred = (a != 0.0f) || (j == i);
        const unsigned mask = __ballot_sync(0xffffffffu, pred);
        if (pred) {
            const int idx = base + __popc(mask & ((1u << lane) - 1u));
            if (idx < NNZ_MAX) {
                g_col[idx] = j;
                const float v = a + ((j == i) ? 1.0f : 0.0f);
                g_val[idx] = di * g_dinv[j] * v;
            }
        }
        base += __popc(mask);
    }
}

__global__ void xT_kernel(const float* __restrict__ x) {
    const int idx = blockIdx.x * blockDim.x + threadIdx.x;
    if (idx >= NN * 96) return;
    const int n = idx / 96;
    const int k = idx % 96;
    const int t = k >> 1;
    const int c = k & 1;
    g_xT[idx] = __ldg(&x[t * (NN * INW) + n * INW + c]);
}

__global__ void ax_kernel() {
    const int i = blockIdx.x;
    const int k = threadIdx.x;  // 0..95
    const int p0 = g_rowptr[i], p1 = g_rowptr[i + 1];
    float acc = 0.0f;
    for (int p = p0; p < p1; ++p)
        acc = fmaf(g_val[p], g_xT[g_col[p] * 96 + k], acc);
    g_AX[i * 96 + k] = acc;
}

__global__ void zero_kernel() {
    const int idx = blockIdx.x * blockDim.x + threadIdx.x;
    if (idx < NN * HH) {
        g_h0[0][idx] = 0.0f; g_c0[0][idx] = 0.0f;
        g_h1[0][idx] = 0.0f; g_c1[0][idx] = 0.0f;
    }
}

// ---------------- cell bodies ----------------------------------------------------
// Shared buffer union (floats), 16B aligned; SBUF_F = 8848 (35.4 KB):
//   cell0: sAhT[64][S0]@0, sHT[64][S0]@2304, sXAT[2][36]@4608, sXIT[2][36]@4680,
//          scol[2048](int)@4752, sval[2048]@6800
//   cell0 phase C: comb[32][256]@0 (8192 floats, overlays everything)
//   cell1: sAiT[64][S1]@0, sAhT@1280, sIT@2560, sHT@3840,
//          scol[1024](int)@5120, sval[1024]@6144
//   cell1 phase C: comb[16][256]@0
// Activation layout is TRANSPOSED (row index contiguous) so one LDS.128 yields
// 4 consecutive rows of one mm -> two f32x2 row-pair operands.
#define SBUF_F 8848

__device__ __forceinline__ void cell0_body(
    float* __restrict__ sbuf, int row0, int t,
    const float* __restrict__ h_in, const float* __restrict__ c_in,
    float* __restrict__ h_out, float* __restrict__ c_out,
    const float* __restrict__ Wgi, const float* __restrict__ Wgh,
    const float* __restrict__ Wli, const float* __restrict__ Wlh,
    const float* __restrict__ bgi, const float* __restrict__ bgh,
    const float* __restrict__ bli, const float* __restrict__ blh)
{
    const int tid = threadIdx.x;
    const int m   = tid & 63;
    const int rg  = tid >> 6;

    float* sAhT = sbuf;            // [64][S0]  (mm-major, rows contiguous)
    float* sHT  = sbuf + 2304;     // [64][S0]
    float* sXAT = sbuf + 4608;     // [2][36]
    float* sXIT = sbuf + 4680;     // [2][36]
    int*   scol = (int*)(sbuf + 4752);   // [CAP0]
    float* sval = sbuf + 6800;           // [CAP0]
    float* scomb = sbuf;                 // [32][256] overlay after GEMM

    // Stage this block's CSR segment into smem (coalesced, high MLP)
    const int base = g_rowptr[row0];
    const int tot  = g_rowptr[row0 + RT0] - base;
    const int nst  = (tot < CAP0) ? tot : CAP0;
    for (int q = tid; q < nst; q += 256) {
        scol[q] = g_col[base + q];
        sval[q] = g_val[base + q];
    }
    __syncthreads();

    // Gather phase: deep-unrolled independent gathers (MLP ~8), transposed store
    for (int r = rg; r < RT0; r += 4) {
        const int i = row0 + r;
        sHT[m * S0 + r] = __ldg(&h_in[i * HH + m]);
        int       p  = g_rowptr[i]     - base;
        const int pe = g_rowptr[i + 1] - base;
        const int ps = (pe < CAP0) ? pe : CAP0;
        float a0 = 0.0f, a1 = 0.0f, a2 = 0.0f, a3 = 0.0f;
        for (; p + 8 <= ps; p += 8) {
            const int   c0 = scol[p    ], c1 = scol[p + 1];
            const int   c2 = scol[p + 2], c3 = scol[p + 3];
            const int   c4 = scol[p + 4], c5 = scol[p + 5];
            const int   c6 = scol[p + 6], c7 = scol[p + 7];
            const float v0 = sval[p    ], v1 = sval[p + 1];
            const float v2 = sval[p + 2], v3 = sval[p + 3];
            const float v4 = sval[p + 4], v5 = sval[p + 5];
            const float v6 = sval[p + 6], v7 = sval[p + 7];
            a0 = fmaf(v0, __ldg(&h_in[c0 * HH + m]), a0);
            a1 = fmaf(v1, __ldg(&h_in[c1 * HH + m]), a1);
            a2 = fmaf(v2, __ldg(&h_in[c2 * HH + m]), a2);
            a3 = fmaf(v3, __ldg(&h_in[c3 * HH + m]), a3);
            a0 = fmaf(v4, __ldg(&h_in[c4 * HH + m]), a0);
            a1 = fmaf(v5, __ldg(&h_in[c5 * HH + m]), a1);
            a2 = fmaf(v6, __ldg(&h_in[c6 * HH + m]), a2);
            a3 = fmaf(v7, __ldg(&h_in[c7 * HH + m]), a3);
        }
        for (; p < ps; ++p)
            a0 = fmaf(sval[p], __ldg(&h_in[scol[p] * HH + m]), a0);
        for (; p < pe; ++p)   // overflow fallback (exact; normally never runs)
            a0 = fmaf(g_val[base + p], __ldg(&h_in[g_col[base + p] * HH + m]), a0);
        sAhT[m * S0 + r] = (a0 + a1) + (a2 + a3);
        if (m < 2) {
            sXAT[m * 36 + r] = g_AX[i * 96 + 2 * t + m];
            sXIT[m * 36 + r] = g_xT[i * 96 + 2 * t + m];
        }
    }
    __syncthreads();

    // GEMM phase (f32x2): thread owns gate-column kk2 = tid; 16 row-pairs.
    const int kk2 = tid;
    unsigned long long acc2[RT0 / 2];
    {
        const float bb = __ldg(&bgi[kk2]) + __ldg(&bgh[kk2]) + __ldg(&bli[kk2]) + __ldg(&blh[kk2]);
        unsigned long long bb2; PACK2(bb2, bb);
#pragma unroll
        for (int rp = 0; rp < RT0 / 2; ++rp) acc2[rp] = bb2;
    }

#pragma unroll 1
    for (int mm = 0; mm < HH; mm += 4) {
        unsigned long long wgp[4], wlp[4];
#pragma unroll
        for (int u = 0; u < 4; ++u) {
            const float wg = __ldg(&Wgh[(mm + u) * G4 + kk2]);
            const float wl = __ldg(&Wlh[(mm + u) * G4 + kk2]);
            PACK2(wgp[u], wg);
            PACK2(wlp[u], wl);
        }
#pragma unroll
        for (int q = 0; q < RT0 / 4; ++q) {        // row quads: rows 4q..4q+3
#pragma unroll
            for (int u = 0; u < 4; ++u) {
                const ulonglong2 va = *(const ulonglong2*)&sAhT[(mm + u) * S0 + 4 * q];
                const ulonglong2 vh = *(const ulonglong2*)&sHT [(mm + u) * S0 + 4 * q];
                FMA2(acc2[2 * q    ], va.x, wgp[u]);
                FMA2(acc2[2 * q + 1], va.y, wgp[u]);
                FMA2(acc2[2 * q    ], vh.x, wlp[u]);
                FMA2(acc2[2 * q + 1], vh.y, wlp[u]);
            }
        }
    }
    {   // input terms (K = 2 each), packed per row-pair
        unsigned long long wap[2], wip[2];
#pragma unroll
        for (int c = 0; c < 2; ++c) {
            const float wa = __ldg(&Wgi[c * G4 + kk2]);
            const float wi = __ldg(&Wli[c * G4 + kk2]);
            PACK2(wap[c], wa);
            PACK2(wip[c], wi);
        }
#pragma unroll
        for (int rp = 0; rp < RT0 / 2; ++rp) {
#pragma unroll
            for (int c = 0; c < 2; ++c) {
                const unsigned long long xa = *(const unsigned long long*)&sXAT[c * 36 + 2 * rp];
                const unsigned long long xi = *(const unsigned long long*)&sXIT[c * 36 + 2 * rp];
                FMA2(acc2[rp], xa, wap[c]);
                FMA2(acc2[rp], xi, wip[c]);
            }
        }
    }

    // Elementwise phase: full comb overlay, 2 syncs total.
    __syncthreads();   // all GEMM shared reads complete; sbuf reusable
#pragma unroll
    for (int rp = 0; rp < RT0 / 2; ++rp) {
        float lo, hi;
        UNPACK2(lo, hi, acc2[rp]);
        scomb[(2 * rp    ) * 256 + kk2] = lo;
        scomb[(2 * rp + 1) * 256 + kk2] = hi;
    }
    __syncthreads();
    {
        const int rw = tid >> 5;             // warp w -> row offset
        const int hh = (tid & 31) * 2;       // 2 hidden units per lane
#pragma unroll
        for (int pass = 0; pass < RT0 / 8; ++pass) {
            const int row = pass * 8 + rw;
            const int i   = row0 + row;
            const float2 ci = *(const float2*)&scomb[row * 256 + hh      ];
            const float2 cf = *(const float2*)&scomb[row * 256 + hh +  64];
            const float2 co = *(const float2*)&scomb[row * 256 + hh + 128];
            const float2 cg = *(const float2*)&scomb[row * 256 + hh + 192];
            const float2 cold = *(const float2*)&c_in[i * HH + hh];
            float2 cn, hn;
            cn.x = fsigm(cf.x) * cold.x + fsigm(ci.x) * ftanh(cg.x);
            cn.y = fsigm(cf.y) * cold.y + fsigm(ci.y) * ftanh(cg.y);
            hn.x = fsigm(co.x) * ftanh(cn.x);
            hn.y = fsigm(co.y) * ftanh(cn.y);
            *(float2*)&c_out[i * HH + hh] = cn;
            *(float2*)&h_out[i * HH + hh] = hn;
        }
    }
}

__device__ __forceinline__ void cell1_body(
    float* __restrict__ sbuf, int row0,
    const float* __restrict__ inp,  const float* __restrict__ h_in,
    const float* __restrict__ c_in,
    float* __restrict__ h_out, float* __restrict__ c_out,
    const float* __restrict__ Wgi, const float* __restrict__ Wgh,
    const float* __restrict__ Wli, const float* __restrict__ Wlh,
    const float* __restrict__ bgi, const float* __restrict__ bgh,
    const float* __restrict__ bli, const float* __restrict__ blh)
{
    const int tid = threadIdx.x;
    const int m   = tid & 63;
    const int rg  = tid >> 6;

    float* sAiT = sbuf;            // [64][S1]
    float* sAhT = sbuf + 1280;     // [64][S1]
    float* sIT  = sbuf + 2560;     // [64][S1]
    float* sHT  = sbuf + 3840;     // [64][S1]
    int*   scol = (int*)(sbuf + 5120);   // [CAP1]
    float* sval = sbuf + 6144;           // [CAP1]
    float* scomb = sbuf;                 // [16][256] overlay after GEMM

    // Stage this block's CSR segment into smem
    const int base = g_rowptr[row0];
    const int tot  = g_rowptr[row0 + RT1] - base;
    const int nst  = (tot < CAP1) ? tot : CAP1;
    for (int q = tid; q < nst; q += 256) {
        scol[q] = g_col[base + q];
        sval[q] = g_val[base + q];
    }
    __syncthreads();

    for (int r = rg; r < RT1; r += 4) {
        const int i = row0 + r;
        sIT[m * S1 + r] = __ldg(&inp [i * HH + m]);
        sHT[m * S1 + r] = __ldg(&h_in[i * HH + m]);
        int       p  = g_rowptr[i]     - base;
        const int pe = g_rowptr[i + 1] - base;
        const int ps = (pe < CAP1) ? pe : CAP1;
        float a0 = 0.0f, a1 = 0.0f, a2 = 0.0f, a3 = 0.0f;
        float b0 = 0.0f, b1 = 0.0f, b2 = 0.0f, b3 = 0.0f;
        for (; p + 4 <= ps; p += 4) {
            const int   c0 = scol[p    ], c1 = scol[p + 1];
            const int   c2 = scol[p + 2], c3 = scol[p + 3];
            const float v0 = sval[p    ], v1 = sval[p + 1];
            const float v2 = sval[p + 2], v3 = sval[p + 3];
            a0 = fmaf(v0, __ldg(&inp [c0 * HH + m]), a0);
            b0 = fmaf(v0, __ldg(&h_in[c0 * HH + m]), b0);
            a1 = fmaf(v1, __ldg(&inp [c1 * HH + m]), a1);
            b1 = fmaf(v1, __ldg(&h_in[c1 * HH + m]), b1);
            a2 = fmaf(v2, __ldg(&inp [c2 * HH + m]), a2);
            b2 = fmaf(v2, __ldg(&h_in[c2 * HH + m]), b2);
            a3 = fmaf(v3, __ldg(&inp [c3 * HH + m]), a3);
            b3 = fmaf(v3, __ldg(&h_in[c3 * HH + m]), b3);
        }
        for (; p < ps; ++p) {
            const int   c = scol[p];
            const float v = sval[p];
            a0 = fmaf(v, __ldg(&inp [c * HH + m]), a0);
            b0 = fmaf(v, __ldg(&h_in[c * HH + m]), b0);
        }
        for (; p < pe; ++p) {  // overflow fallback (exact; normally never runs)
            const int   c = g_col[base + p];
            const float v = g_val[base + p];
            a0 = fmaf(v, __ldg(&inp [c * HH + m]), a0);
            b0 = fmaf(v, __ldg(&h_in[c * HH + m]), b0);
        }
        sAiT[m * S1 + r] = (a0 + a1) + (a2 + a3);
        sAhT[m * S1 + r] = (b0 + b1) + (b2 + b3);
    }
    __syncthreads();

    // GEMM phase (f32x2): 4 matrices, 8 row-pairs.
    const int kk2 = tid;
    unsigned long long acc2[RT1 / 2];
    {
        const float bb = __ldg(&bgi[kk2]) + __ldg(&bgh[kk2]) + __ldg(&bli[kk2]) + __ldg(&blh[kk2]);
        unsigned long long bb2; PACK2(bb2, bb);
#pragma unroll
        for (int rp = 0; rp < RT1 / 2; ++rp) acc2[rp] = bb2;
    }

#pragma unroll 1
    for (int mm = 0; mm < HH; mm += 4) {
        unsigned long long w1p[4], w2p[4], w3p[4], w4p[4];
#pragma unroll
        for (int u = 0; u < 4; ++u) {
            const float w1 = __ldg(&Wgi[(mm + u) * G4 + kk2]);
            const float w2 = __ldg(&Wgh[(mm + u) * G4 + kk2]);
            const float w3 = __ldg(&Wli[(mm + u) * G4 + kk2]);
            const float w4 = __ldg(&Wlh[(mm + u) * G4 + kk2]);
            PACK2(w1p[u], w1);
            PACK2(w2p[u], w2);
            PACK2(w3p[u], w3);
            PACK2(w4p[u], w4);
        }
#pragma unroll
        for (int q = 0; q < RT1 / 4; ++q) {        // row quads
#pragma unroll
            for (int u = 0; u < 4; ++u) {
                const ulonglong2 va = *(const ulonglong2*)&sAiT[(mm + u) * S1 + 4 * q];
                const ulonglong2 vb = *(const ulonglong2*)&sAhT[(mm + u) * S1 + 4 * q];
                const ulonglong2 vi = *(const ulonglong2*)&sIT [(mm + u) * S1 + 4 * q];
                const ulonglong2 vh = *(const ulonglong2*)&sHT [(mm + u) * S1 + 4 * q];
                FMA2(acc2[2 * q    ], va.x, w1p[u]);
                FMA2(acc2[2 * q + 1], va.y, w1p[u]);
                FMA2(acc2[2 * q    ], vb.x, w2p[u]);
                FMA2(acc2[2 * q + 1], vb.y, w2p[u]);
                FMA2(acc2[2 * q    ], vi.x, w3p[u]);
                FMA2(acc2[2 * q + 1], vi.y, w3p[u]);
                FMA2(acc2[2 * q    ], vh.x, w4p[u]);
                FMA2(acc2[2 * q + 1], vh.y, w4p[u]);
            }
        }
    }

    // Elementwise phase: full comb overlay, 2 syncs total.
    __syncthreads();
#pragma unroll
    for (int rp = 0; rp < RT1 / 2; ++rp) {
        float lo, hi;
        UNPACK2(lo, hi, acc2[rp]);
        scomb[(2 * rp    ) * 256 + kk2] = lo;
        scomb[(2 * rp + 1) * 256 + kk2] = hi;
    }
    __syncthreads();
    {
        const int rw = tid >> 5;
        const int hh = (tid & 31) * 2;
#pragma unroll
        for (int pass = 0; pass < RT1 / 8; ++pass) {
            const int row = pass * 8 + rw;
            const int i   = row0 + row;
            const float2 ci = *(const float2*)&scomb[row * 256 + hh      ];
            const float2 cf = *(const float2*)&scomb[row * 256 + hh +  64];
            const float2 co = *(const float2*)&scomb[row * 256 + hh + 128];
            const float2 cg = *(const float2*)&scomb[row * 256 + hh + 192];
            const float2 cold = *(const float2*)&c_in[i * HH + hh];
            float2 cn, hn;
            cn.x = fsigm(cf.x) * cold.x + fsigm(ci.x) * ftanh(cg.x);
            cn.y = fsigm(cf.y) * cold.y + fsigm(ci.y) * ftanh(cg.y);
            hn.x = fsigm(co.x) * ftanh(cn.x);
            hn.y = fsigm(co.y) * ftanh(cn.y);
            *(float2*)&c_out[i * HH + hh] = cn;
            *(float2*)&h_out[i * HH + hh] = hn;
        }
    }
}

// ---------------- kernels --------------------------------------------------------

// Standalone cell0 (first step only)
__global__ void __launch_bounds__(256, 3) cell0_kernel(
    int t, int rd,
    const float* __restrict__ Wgi, const float* __restrict__ Wgh,
    const float* __restrict__ Wli, const float* __restrict__ Wlh,
    const float* __restrict__ bgi, const float* __restrict__ bgh,
    const float* __restrict__ bli, const float* __restrict__ blh)
{
    __shared__ __align__(16) float sbuf[SBUF_F];
    cell0_body(sbuf, blockIdx.x * RT0, t,
               g_h0[rd], g_c0[rd], g_h0[rd ^ 1], g_c0[rd ^ 1],
               Wgi, Wgh, Wli, Wlh, bgi, bgh, bli, blh);
}

// Standalone cell1 (last step only)
__global__ void __launch_bounds__(256, 3) cell1_kernel(
    int rd,
    const float* __restrict__ Wgi, const float* __restrict__ Wgh,
    const float* __restrict__ Wli, const float* __restrict__ Wlh,
    const float* __restrict__ bgi, const float* __restrict__ bgh,
    const float* __restrict__ bli, const float* __restrict__ blh)
{
    __shared__ __align__(16) float sbuf[SBUF_F];
    cell1_body(sbuf, blockIdx.x * RT1,
               g_h0[rd ^ 1], g_h1[rd], g_c1[rd], g_h1[rd ^ 1], g_c1[rd ^ 1],
               Wgi, Wgh, Wli, Wlh, bgi, bgh, bli, blh);
}

// Fused: cell1(tnext-1) runs concurrently with cell0(tnext).
__global__ void __launch_bounds__(256, 3) step_kernel(
    int tnext,
    const float* __restrict__ Wgi0, const float* __restrict__ Wgh0,
    const float* __restrict__ Wli0, const float* __restrict__ Wlh0,
    const float* __restrict__ bgi0, const float* __restrict__ bgh0,
    const float* __restrict__ bli0, const float* __restrict__ blh0,
    const float* __restrict__ Wgi1, const float* __restrict__ Wgh1,
    const float* __restrict__ Wli1, const float* __restrict__ Wlh1,
    const float* __restrict__ bgi1, const float* __restrict__ bgh1,
    const float* __restrict__ bli1, const float* __restrict__ blh1)
{
    __shared__ __align__(16) float sbuf[SBUF_F];
    const int rd0 = tnext & 1;         // cell0 parity at step tnext
    const int rd1 = rd0 ^ 1;           // cell1 parity at step tnext-1
    if (blockIdx.x < NB0) {
        cell0_body(sbuf, blockIdx.x * RT0, tnext,
                   g_h0[rd0], g_c0[rd0], g_h0[rd0 ^ 1], g_c0[rd0 ^ 1],
                   Wgi0, Wgh0, Wli0, Wlh0, bgi0, bgh0, bli0, blh0);
    } else {
        cell1_body(sbuf, (blockIdx.x - NB0) * RT1,
                   g_h0[rd0],                  // inp = h0(tnext-1)
                   g_h1[rd1], g_c1[rd1], g_h1[rd1 ^ 1], g_c1[rd1 ^ 1],
                   Wgi1, Wgh1, Wli1, Wlh1, bgi1, bgh1, bli1, blh1);
    }
}

// Final projection: out[i,p] = h1[i,:] @ outW[:,p] + outb[p]
__global__ void out_kernel(const float* __restrict__ outW,
                           const float* __restrict__ outb,
                           float* __restrict__ out)
{
    const int idx = blockIdx.x * blockDim.x + threadIdx.x;
    if (idx >= NN * PP) return;
    const int i = idx / PP;
    const int p = idx % PP;
    const float* h = &g_h1[0][i * HH];   // parity 0 after 48 steps
    float acc = __ldg(&outb[p]);
#pragma unroll
    for (int mm = 0; mm < HH; ++mm)
        acc = fmaf(h[mm], __ldg(&outW[mm * PP + p]), acc);
    out[idx] = acc;
}

// ---------------- launch --------------------------------------------------------
extern "C" void kernel_launch(void* const* d_in, const int* in_sizes, int n_in,
                              void* d_out, int out_size) {
    const float* x     = (const float*)d_in[0];
    const float* adj   = (const float*)d_in[1];
    const float* gcWi0 = (const float*)d_in[2];  const float* gcbi0 = (const float*)d_in[3];
    const float* gcWh0 = (const float*)d_in[4];  const float* gcbh0 = (const float*)d_in[5];
    const float* liWi0 = (const float*)d_in[6];  const float* libi0 = (const float*)d_in[7];
    const float* liWh0 = (const float*)d_in[8];  const float* libh0 = (const float*)d_in[9];
    const float* gcWi1 = (const float*)d_in[10]; const float* gcbi1 = (const float*)d_in[11];
    const float* gcWh1 = (const float*)d_in[12]; const float* gcbh1 = (const float*)d_in[13];
    const float* liWi1 = (const float*)d_in[14]; const float* libi1 = (const float*)d_in[15];
    const float* liWh1 = (const float*)d_in[16]; const float* libh1 = (const float*)d_in[17];
    const float* outW  = (const float*)d_in[18]; const float* outb  = (const float*)d_in[19];
    float* out = (float*)d_out;

    // Preprocessing (captured in the graph; deterministic)
    degree_kernel<<<NN, 128>>>(adj);
    scan_kernel<<<1, 1024>>>();
    fill_kernel<<<(NN * 32 + 255) / 256, 256>>>(adj);
    xT_kernel<<<(NN * 96 + 255) / 256, 256>>>(x);
    ax_kernel<<<NN, 96>>>();
    zero_kernel<<<(NN * HH + 255) / 256, 256>>>();

    // Step 0: cell0 alone (reads zeroed h0[0], writes h0[1])
    cell0_kernel<<<NB0, 256>>>(0, 0,
        gcWi0, gcWh0, liWi0, liWh0, gcbi0, gcbh0, libi0, libh0);

    // Steps: fused cell1(t-1) || cell0(t) for t = 1..47
    for (int tnext = 1; tnext < TT; ++tnext) {
        step_kernel<<<NB0 + NB1, 256>>>(tnext,
            gcWi0, gcWh0, liWi0, liWh0, gcbi0, gcbh0, libi0, libh0,
            gcWi1, gcWh1, liWi1, liWh1, gcbi1, gcbh1, libi1, libh1);
    }

    // Last: cell1 for step 47 (rd = 47 & 1 = 1)
    cell1_kernel<<<NB1, 256>>>(1,
        gcWi1, gcWh1, liWi1, liWh1, gcbi1, gcbh1, libi1, libh1);

    out_kernel<<<(NN * PP + 255) / 256, 256>>>(outW, outb, out);
}

// round 13
// speedup vs baseline: 1.9995x; 1.0463x over previous
#include <cuda_runtime.h>
#include <cuda_bf16.h>
#include <math.h>

// Problem constants
#define NN    4096          // graph nodes
#define TT    48            // timesteps
#define HH    64            // hidden
#define INW   2             // input width
#define PP    12            // output width
#define G4    256           // 4*H
#define RT0   32            // rows per block, cell0
#define RT1   16            // rows per block, cell1
#define NB0   (NN / RT0)    // 128 blocks for cell0
#define NB1   (NN / RT1)    // 256 blocks for cell1
#define NBT   (NB0 + NB1)   // 384 persistent blocks (<= 148 SM * 3 occ = 444)
#define CAP0  2048          // staged nnz cap, cell0 (expected ~1344/block)
#define CAP1  1024          // staged nnz cap, cell1 (expected ~672/block)
#define S0    36            // padded row stride (floats) cell0
#define S1    20            // padded row stride cell1

#define NNZ_MAX (1 << 19)

// ---------------- device scratch -------------------------------------------------
__device__ int   g_rowptr[NN + 1];
__device__ int   g_rowcnt[NN];
__device__ int   g_col[NNZ_MAX];
__device__ float g_val[NNZ_MAX];
__device__ float g_dinv[NN];
__device__ float g_xT[NN * 96];   // x transposed: [node][t*2+c]
__device__ float g_AX[NN * 96];   // A @ x, same layout
__device__ float g_h0[2][NN * HH];
__device__ float g_c0[2][NN * HH];
__device__ float g_h1[2][NN * HH];
__device__ float g_c1[2][NN * HH];

// Grid barrier state (zeroed by zero_kernel every launch -> replay-safe)
__device__ unsigned g_bar_cnt;
__device__ unsigned g_bar_epoch;

// Fast gates: MUFU-based. Inf-safe: __expf(big)=inf -> __fdividef(2,inf)=0.
__device__ __forceinline__ float fsigm(float x) {
    return __fdividef(1.0f, 1.0f + __expf(-x));
}
__device__ __forceinline__ float ftanh(float x) {
    return 1.0f - __fdividef(2.0f, __expf(2.0f * x) + 1.0f);
}

// Packed f32x2 helpers (Blackwell dual-rate fp32; only reachable via PTX)
#define FMA2(acc, a, b) \
    asm("fma.rn.f32x2 %0, %1, %2, %0;" : "+l"(acc) : "l"(a), "l"(b))
#define PACK2(out, x) \
    asm("mov.b64 %0, {%1, %1};" : "=l"(out) : "f"(x))
#define UNPACK2(lo, hi, in) \
    asm("mov.b64 {%0, %1}, %2;" : "=f"(lo), "=f"(hi) : "l"(in))

// Device-wide barrier (all NBT blocks co-resident by construction).
__device__ __forceinline__ void grid_sync(unsigned target) {
    __syncthreads();
    if (threadIdx.x == 0) {
        __threadfence();
        const unsigned old = atomicAdd(&g_bar_cnt, 1u);
        if (old == (unsigned)(NBT - 1)) {
            atomicExch(&g_bar_cnt, 0u);
            __threadfence();
            atomicAdd(&g_bar_epoch, 1u);
        } else {
            while (atomicAdd(&g_bar_epoch, 0u) != target) { __nanosleep(64); }
        }
        __threadfence();
    }
    __syncthreads();
}

// ---------------- preprocessing -------------------------------------------------
__global__ void degree_kernel(const float* __restrict__ adj) {
    const int i = blockIdx.x;
    const int tid = threadIdx.x;
    const float* row = adj + (size_t)i * NN;
    float d = 0.0f;
    int cnt = 0;
    for (int j = tid; j < NN; j += blockDim.x) {
        const float a = __ldg(&row[j]);
        d += a;
        cnt += (a != 0.0f && j != i) ? 1 : 0;
    }
    __shared__ float sd[128];
    __shared__ int   sc[128];
    sd[tid] = d; sc[tid] = cnt;
    __syncthreads();
    for (int off = 64; off > 0; off >>= 1) {
        if (tid < off) { sd[tid] += sd[tid + off]; sc[tid] += sc[tid + off]; }
        __syncthreads();
    }
    if (tid == 0) {
        const float dd = sd[0] + 1.0f;
        g_dinv[i]   = 1.0f / sqrtf(dd);
        g_rowcnt[i] = sc[0] + 1;
    }
}

__global__ void scan_kernel() {
    __shared__ int s[1024];
    const int tid = threadIdx.x;
    int c[4];
    int sum = 0;
#pragma unroll
    for (int u = 0; u < 4; ++u) { c[u] = g_rowcnt[tid * 4 + u]; sum += c[u]; }
    s[tid] = sum;
    __syncthreads();
    for (int off = 1; off < 1024; off <<= 1) {
        const int v = (tid >= off) ? s[tid - off] : 0;
        __syncthreads();
        s[tid] += v;
        __syncthreads();
    }
    int excl = s[tid] - sum;
#pragma unroll
    for (int u = 0; u < 4; ++u) { g_rowptr[tid * 4 + u] = excl; excl += c[u]; }
    if (tid == 1023) g_rowptr[NN] = s[1023];
}

__global__ void fill_kernel(const float* __restrict__ adj) {
    const int w = (blockIdx.x * blockDim.x + threadIdx.x) >> 5;
    const int lane = threadIdx.x & 31;
    if (w >= NN) return;
    const int i = w;
    const float* row = adj + (size_t)i * NN;
    const float di = g_dinv[i];
    int base = g_rowptr[i];
    for (int j0 = 0; j0 < NN; j0 += 32) {
        const int j = j0 + lane;
        const float a = __ldg(&row[j]);
        const bool pred = (a != 0.0f) || (j == i);
        const unsigned mask = __ballot_sync(0xffffffffu, pred);
        if (pred) {
            const int idx = base + __popc(mask & ((1u << lane) - 1u));
            if (idx < NNZ_MAX) {
                g_col[idx] = j;
                const float v = a + ((j == i) ? 1.0f : 0.0f);
                g_val[idx] = di * g_dinv[j] * v;
            }
        }
        base += __popc(mask);
    }
}

__global__ void xT_kernel(const float* __restrict__ x) {
    const int idx = blockIdx.x * blockDim.x + threadIdx.x;
    if (idx >= NN * 96) return;
    const int n = idx / 96;
    const int k = idx % 96;
    const int t = k >> 1;
    const int c = k & 1;
    g_xT[idx] = __ldg(&x[t * (NN * INW) + n * INW + c]);
}

__global__ void ax_kernel() {
    const int i = blockIdx.x;
    const int k = threadIdx.x;  // 0..95
    const int p0 = g_rowptr[i], p1 = g_rowptr[i + 1];
    float acc = 0.0f;
    for (int p = p0; p < p1; ++p)
        acc = fmaf(g_val[p], g_xT[g_col[p] * 96 + k], acc);
    g_AX[i * 96 + k] = acc;
}

__global__ void zero_kernel() {
    const int idx = blockIdx.x * blockDim.x + threadIdx.x;
    if (idx == 0) { g_bar_cnt = 0u; g_bar_epoch = 0u; }
    if (idx < NN * HH) {
        g_h0[0][idx] = 0.0f; g_c0[0][idx] = 0.0f;
        g_h1[0][idx] = 0.0f; g_c1[0][idx] = 0.0f;
    }
}

// ---------------- cell bodies ----------------------------------------------------
// Shared buffer union (floats), 16B aligned; SBUF_F = 8848 (35.4 KB):
//   cell0: sAhT[64][S0]@0, sHT[64][S0]@2304, sXAT[2][36]@4608, sXIT[2][36]@4680,
//          scol[2048](int)@4752, sval[2048]@6800
//   cell0 phase C: comb[32][256]@0 (8192 floats, overlays everything)
//   cell1: sAiT[64][S1]@0, sAhT@1280, sIT@2560, sHT@3840,
//          scol[1024](int)@5120, sval[1024]@6144
//   cell1 phase C: comb[16][256]@0
// Activation layout is TRANSPOSED (row index contiguous) so one LDS.128 yields
// 4 consecutive rows of one mm -> two f32x2 row-pair operands.
#define SBUF_F 8848

__device__ __forceinline__ void cell0_body(
    float* __restrict__ sbuf, int row0, int t,
    const float* __restrict__ h_in, const float* __restrict__ c_in,
    float* __restrict__ h_out, float* __restrict__ c_out,
    const float* __restrict__ Wgi, const float* __restrict__ Wgh,
    const float* __restrict__ Wli, const float* __restrict__ Wlh,
    const float* __restrict__ bgi, const float* __restrict__ bgh,
    const float* __restrict__ bli, const float* __restrict__ blh)
{
    const int tid = threadIdx.x;
    const int m   = tid & 63;
    const int rg  = tid >> 6;

    float* sAhT = sbuf;            // [64][S0]  (mm-major, rows contiguous)
    float* sHT  = sbuf + 2304;     // [64][S0]
    float* sXAT = sbuf + 4608;     // [2][36]
    float* sXIT = sbuf + 4680;     // [2][36]
    int*   scol = (int*)(sbuf + 4752);   // [CAP0]
    float* sval = sbuf + 6800;           // [CAP0]
    float* scomb = sbuf;                 // [32][256] overlay after GEMM

    // Stage this block's CSR segment into smem (coalesced, high MLP; L1-warm
    // after the first step inside the persistent kernel)
    const int base = g_rowptr[row0];
    const int tot  = g_rowptr[row0 + RT0] - base;
    const int nst  = (tot < CAP0) ? tot : CAP0;
    for (int q = tid; q < nst; q += 256) {
        scol[q] = g_col[base + q];
        sval[q] = g_val[base + q];
    }
    __syncthreads();

    // Gather phase: deep-unrolled independent gathers (MLP ~8), transposed store
    for (int r = rg; r < RT0; r += 4) {
        const int i = row0 + r;
        sHT[m * S0 + r] = __ldg(&h_in[i * HH + m]);
        int       p  = g_rowptr[i]     - base;
        const int pe = g_rowptr[i + 1] - base;
        const int ps = (pe < CAP0) ? pe : CAP0;
        float a0 = 0.0f, a1 = 0.0f, a2 = 0.0f, a3 = 0.0f;
        for (; p + 8 <= ps; p += 8) {
            const int   c0 = scol[p    ], c1 = scol[p + 1];
            const int   c2 = scol[p + 2], c3 = scol[p + 3];
            const int   c4 = scol[p + 4], c5 = scol[p + 5];
            const int   c6 = scol[p + 6], c7 = scol[p + 7];
            const float v0 = sval[p    ], v1 = sval[p + 1];
            const float v2 = sval[p + 2], v3 = sval[p + 3];
            const float v4 = sval[p + 4], v5 = sval[p + 5];
            const float v6 = sval[p + 6], v7 = sval[p + 7];
            a0 = fmaf(v0, __ldg(&h_in[c0 * HH + m]), a0);
            a1 = fmaf(v1, __ldg(&h_in[c1 * HH + m]), a1);
            a2 = fmaf(v2, __ldg(&h_in[c2 * HH + m]), a2);
            a3 = fmaf(v3, __ldg(&h_in[c3 * HH + m]), a3);
            a0 = fmaf(v4, __ldg(&h_in[c4 * HH + m]), a0);
            a1 = fmaf(v5, __ldg(&h_in[c5 * HH + m]), a1);
            a2 = fmaf(v6, __ldg(&h_in[c6 * HH + m]), a2);
            a3 = fmaf(v7, __ldg(&h_in[c7 * HH + m]), a3);
        }
        for (; p < ps; ++p)
            a0 = fmaf(sval[p], __ldg(&h_in[scol[p] * HH + m]), a0);
        for (; p < pe; ++p)   // overflow fallback (exact; normally never runs)
            a0 = fmaf(g_val[base + p], __ldg(&h_in[g_col[base + p] * HH + m]), a0);
        sAhT[m * S0 + r] = (a0 + a1) + (a2 + a3);
        if (m < 2) {
            sXAT[m * 36 + r] = g_AX[i * 96 + 2 * t + m];
            sXIT[m * 36 + r] = g_xT[i * 96 + 2 * t + m];
        }
    }
    __syncthreads();

    // GEMM phase (f32x2): thread owns gate-column kk2 = tid; 16 row-pairs.
    const int kk2 = tid;
    unsigned long long acc2[RT0 / 2];
    {
        const float bb = __ldg(&bgi[kk2]) + __ldg(&bgh[kk2]) + __ldg(&bli[kk2]) + __ldg(&blh[kk2]);
        unsigned long long bb2; PACK2(bb2, bb);
#pragma unroll
        for (int rp = 0; rp < RT0 / 2; ++rp) acc2[rp] = bb2;
    }

#pragma unroll 1
    for (int mm = 0; mm < HH; mm += 4) {
        unsigned long long wgp[4], wlp[4];
#pragma unroll
        for (int u = 0; u < 4; ++u) {
            const float wg = __ldg(&Wgh[(mm + u) * G4 + kk2]);
            const float wl = __ldg(&Wlh[(mm + u) * G4 + kk2]);
            PACK2(wgp[u], wg);
            PACK2(wlp[u], wl);
        }
#pragma unroll
        for (int q = 0; q < RT0 / 4; ++q) {        // row quads: rows 4q..4q+3
#pragma unroll
            for (int u = 0; u < 4; ++u) {
                const ulonglong2 va = *(const ulonglong2*)&sAhT[(mm + u) * S0 + 4 * q];
                const ulonglong2 vh = *(const ulonglong2*)&sHT [(mm + u) * S0 + 4 * q];
                FMA2(acc2[2 * q    ], va.x, wgp[u]);
                FMA2(acc2[2 * q + 1], va.y, wgp[u]);
                FMA2(acc2[2 * q    ], vh.x, wlp[u]);
                FMA2(acc2[2 * q + 1], vh.y, wlp[u]);
            }
        }
    }
    {   // input terms (K = 2 each), packed per row-pair
        unsigned long long wap[2], wip[2];
#pragma unroll
        for (int c = 0; c < 2; ++c) {
            const float wa = __ldg(&Wgi[c * G4 + kk2]);
            const float wi = __ldg(&Wli[c * G4 + kk2]);
            PACK2(wap[c], wa);
            PACK2(wip[c], wi);
        }
#pragma unroll
        for (int rp = 0; rp < RT0 / 2; ++rp) {
#pragma unroll
            for (int c = 0; c < 2; ++c) {
                const unsigned long long xa = *(const unsigned long long*)&sXAT[c * 36 + 2 * rp];
                const unsigned long long xi = *(const unsigned long long*)&sXIT[c * 36 + 2 * rp];
                FMA2(acc2[rp], xa, wap[c]);
                FMA2(acc2[rp], xi, wip[c]);
            }
        }
    }

    // Elementwise phase: full comb overlay, 2 syncs.
    __syncthreads();   // all GEMM shared reads complete; sbuf reusable
#pragma unroll
    for (int rp = 0; rp < RT0 / 2; ++rp) {
        float lo, hi;
        UNPACK2(lo, hi, acc2[rp]);
        scomb[(2 * rp    ) * 256 + kk2] = lo;
        scomb[(2 * rp + 1) * 256 + kk2] = hi;
    }
    __syncthreads();
    {
        const int rw = tid >> 5;             // warp w -> row offset
        const int hh = (tid & 31) * 2;       // 2 hidden units per lane
#pragma unroll
        for (int pass = 0; pass < RT0 / 8; ++pass) {
            const int row = pass * 8 + rw;
            const int i   = row0 + row;
            const float2 ci = *(const float2*)&scomb[row * 256 + hh      ];
            const float2 cf = *(const float2*)&scomb[row * 256 + hh +  64];
            const float2 co = *(const float2*)&scomb[row * 256 + hh + 128];
            const float2 cg = *(const float2*)&scomb[row * 256 + hh + 192];
            const float2 cold = *(const float2*)&c_in[i * HH + hh];
            float2 cn, hn;
            cn.x = fsigm(cf.x) * cold.x + fsigm(ci.x) * ftanh(cg.x);
            cn.y = fsigm(cf.y) * cold.y + fsigm(ci.y) * ftanh(cg.y);
            hn.x = fsigm(co.x) * ftanh(cn.x);
            hn.y = fsigm(co.y) * ftanh(cn.y);
            *(float2*)&c_out[i * HH + hh] = cn;
            *(float2*)&h_out[i * HH + hh] = hn;
        }
    }
}

__device__ __forceinline__ void cell1_body(
    float* __restrict__ sbuf, int row0,
    const float* __restrict__ inp,  const float* __restrict__ h_in,
    const float* __restrict__ c_in,
    float* __restrict__ h_out, float* __restrict__ c_out,
    const float* __restrict__ Wgi, const float* __restrict__ Wgh,
    const float* __restrict__ Wli, const float* __restrict__ Wlh,
    const float* __restrict__ bgi, const float* __restrict__ bgh,
    const float* __restrict__ bli, const float* __restrict__ blh)
{
    const int tid = threadIdx.x;
    const int m   = tid & 63;
    const int rg  = tid >> 6;

    float* sAiT = sbuf;            // [64][S1]
    float* sAhT = sbuf + 1280;     // [64][S1]
    float* sIT  = sbuf + 2560;     // [64][S1]
    float* sHT  = sbuf + 3840;     // [64][S1]
    int*   scol = (int*)(sbuf + 5120);   // [CAP1]
    float* sval = sbuf + 6144;           // [CAP1]
    float* scomb = sbuf;                 // [16][256] overlay after GEMM

    // Stage this block's CSR segment into smem
    const int base = g_rowptr[row0];
    const int tot  = g_rowptr[row0 + RT1] - base;
    const int nst  = (tot < CAP1) ? tot : CAP1;
    for (int q = tid; q < nst; q += 256) {
        scol[q] = g_col[base + q];
        sval[q] = g_val[base + q];
    }
    __syncthreads();

    for (int r = rg; r < RT1; r += 4) {
        const int i = row0 + r;
        sIT[m * S1 + r] = __ldg(&inp [i * HH + m]);
        sHT[m * S1 + r] = __ldg(&h_in[i * HH + m]);
        int       p  = g_rowptr[i]     - base;
        const int pe = g_rowptr[i + 1] - base;
        const int ps = (pe < CAP1) ? pe : CAP1;
        float a0 = 0.0f, a1 = 0.0f, a2 = 0.0f, a3 = 0.0f;
        float b0 = 0.0f, b1 = 0.0f, b2 = 0.0f, b3 = 0.0f;
        for (; p + 4 <= ps; p += 4) {
            const int   c0 = scol[p    ], c1 = scol[p + 1];
            const int   c2 = scol[p + 2], c3 = scol[p + 3];
            const float v0 = sval[p    ], v1 = sval[p + 1];
            const float v2 = sval[p + 2], v3 = sval[p + 3];
            a0 = fmaf(v0, __ldg(&inp [c0 * HH + m]), a0);
            b0 = fmaf(v0, __ldg(&h_in[c0 * HH + m]), b0);
            a1 = fmaf(v1, __ldg(&inp [c1 * HH + m]), a1);
            b1 = fmaf(v1, __ldg(&h_in[c1 * HH + m]), b1);
            a2 = fmaf(v2, __ldg(&inp [c2 * HH + m]), a2);
            b2 = fmaf(v2, __ldg(&h_in[c2 * HH + m]), b2);
            a3 = fmaf(v3, __ldg(&inp [c3 * HH + m]), a3);
            b3 = fmaf(v3, __ldg(&h_in[c3 * HH + m]), b3);
        }
        for (; p < ps; ++p) {
            const int   c = scol[p];
            const float v = sval[p];
            a0 = fmaf(v, __ldg(&inp [c * HH + m]), a0);
            b0 = fmaf(v, __ldg(&h_in[c * HH + m]), b0);
        }
        for (; p < pe; ++p) {  // overflow fallback (exact; normally never runs)
            const int   c = g_col[base + p];
            const float v = g_val[base + p];
            a0 = fmaf(v, __ldg(&inp [c * HH + m]), a0);
            b0 = fmaf(v, __ldg(&h_in[c * HH + m]), b0);
        }
        sAiT[m * S1 + r] = (a0 + a1) + (a2 + a3);
        sAhT[m * S1 + r] = (b0 + b1) + (b2 + b3);
    }
    __syncthreads();

    // GEMM phase (f32x2): 4 matrices, 8 row-pairs.
    const int kk2 = tid;
    unsigned long long acc2[RT1 / 2];
    {
        const float bb = __ldg(&bgi[kk2]) + __ldg(&bgh[kk2]) + __ldg(&bli[kk2]) + __ldg(&blh[kk2]);
        unsigned long long bb2; PACK2(bb2, bb);
#pragma unroll
        for (int rp = 0; rp < RT1 / 2; ++rp) acc2[rp] = bb2;
    }

#pragma unroll 1
    for (int mm = 0; mm < HH; mm += 4) {
        unsigned long long w1p[4], w2p[4], w3p[4], w4p[4];
#pragma unroll
        for (int u = 0; u < 4; ++u) {
            const float w1 = __ldg(&Wgi[(mm + u) * G4 + kk2]);
            const float w2 = __ldg(&Wgh[(mm + u) * G4 + kk2]);
            const float w3 = __ldg(&Wli[(mm + u) * G4 + kk2]);
            const float w4 = __ldg(&Wlh[(mm + u) * G4 + kk2]);
            PACK2(w1p[u], w1);
            PACK2(w2p[u], w2);
            PACK2(w3p[u], w3);
            PACK2(w4p[u], w4);
        }
#pragma unroll
        for (int q = 0; q < RT1 / 4; ++q) {        // row quads
#pragma unroll
            for (int u = 0; u < 4; ++u) {
                const ulonglong2 va = *(const ulonglong2*)&sAiT[(mm + u) * S1 + 4 * q];
                const ulonglong2 vb = *(const ulonglong2*)&sAhT[(mm + u) * S1 + 4 * q];
                const ulonglong2 vi = *(const ulonglong2*)&sIT [(mm + u) * S1 + 4 * q];
                const ulonglong2 vh = *(const ulonglong2*)&sHT [(mm + u) * S1 + 4 * q];
                FMA2(acc2[2 * q    ], va.x, w1p[u]);
                FMA2(acc2[2 * q + 1], va.y, w1p[u]);
                FMA2(acc2[2 * q    ], vb.x, w2p[u]);
                FMA2(acc2[2 * q + 1], vb.y, w2p[u]);
                FMA2(acc2[2 * q    ], vi.x, w3p[u]);
                FMA2(acc2[2 * q + 1], vi.y, w3p[u]);
                FMA2(acc2[2 * q    ], vh.x, w4p[u]);
                FMA2(acc2[2 * q + 1], vh.y, w4p[u]);
            }
        }
    }

    // Elementwise phase: full comb overlay, 2 syncs.
    __syncthreads();
#pragma unroll
    for (int rp = 0; rp < RT1 / 2; ++rp) {
        float lo, hi;
        UNPACK2(lo, hi, acc2[rp]);
        scomb[(2 * rp    ) * 256 + kk2] = lo;
        scomb[(2 * rp + 1) * 256 + kk2] = hi;
    }
    __syncthreads();
    {
        const int rw = tid >> 5;
        const int hh = (tid & 31) * 2;
#pragma unroll
        for (int pass = 0; pass < RT1 / 8; ++pass) {
            const int row = pass * 8 + rw;
            const int i   = row0 + row;
            const float2 ci = *(const float2*)&scomb[row * 256 + hh      ];
            const float2 cf = *(const float2*)&scomb[row * 256 + hh +  64];
            const float2 co = *(const float2*)&scomb[row * 256 + hh + 128];
            const float2 cg = *(const float2*)&scomb[row * 256 + hh + 192];
            const float2 cold = *(const float2*)&c_in[i * HH + hh];
            float2 cn, hn;
            cn.x = fsigm(cf.x) * cold.x + fsigm(ci.x) * ftanh(cg.x);
            cn.y = fsigm(cf.y) * cold.y + fsigm(ci.y) * ftanh(cg.y);
            hn.x = fsigm(co.x) * ftanh(cn.x);
            hn.y = fsigm(co.y) * ftanh(cn.y);
            *(float2*)&c_out[i * HH + hh] = cn;
            *(float2*)&h_out[i * HH + hh] = hn;
        }
    }
}

// ---------------- persistent recurrence kernel ------------------------------------
// 384 blocks, occ 3 -> whole grid co-resident (<= 444 slots). Blocks 0..NB0-1 are
// cell0 workers; NB0..NBT-1 are cell1 workers. 49 phases; phase ph runs
// cell0(ph) || cell1(ph-1), with a grid barrier after phases 0..TT-1.
// L1 stays warm across all steps (weights, CSR) -- no per-launch flush.
__global__ void __launch_bounds__(256, 3) persist_kernel(
    const float* __restrict__ Wgi0, const float* __restrict__ Wgh0,
    const float* __restrict__ Wli0, const float* __restrict__ Wlh0,
    const float* __restrict__ bgi0, const float* __restrict__ bgh0,
    const float* __restrict__ bli0, const float* __restrict__ blh0,
    const float* __restrict__ Wgi1, const float* __restrict__ Wgh1,
    const float* __restrict__ Wli1, const float* __restrict__ Wlh1,
    const float* __restrict__ bgi1, const float* __restrict__ bgh1,
    const float* __restrict__ bli1, const float* __restrict__ blh1)
{
    __shared__ __align__(16) float sbuf[SBUF_F];
    const bool is_cell0 = (blockIdx.x < NB0);
    const int  row0 = is_cell0 ? (int)blockIdx.x * RT0
                               : ((int)blockIdx.x - NB0) * RT1;
    unsigned ep = 0;
#pragma unroll 1
    for (int ph = 0; ph <= TT; ++ph) {
        if (is_cell0) {
            if (ph < TT) {
                const int rd = ph & 1;
                cell0_body(sbuf, row0, ph,
                           g_h0[rd], g_c0[rd], g_h0[rd ^ 1], g_c0[rd ^ 1],
                           Wgi0, Wgh0, Wli0, Wlh0, bgi0, bgh0, bli0, blh0);
            }
        } else {
            if (ph >= 1) {
                const int rd = (ph - 1) & 1;     // cell1 step s = ph-1
                cell1_body(sbuf, row0,
                           g_h0[rd ^ 1],          // inp = h0 written by cell0(s)
                           g_h1[rd], g_c1[rd], g_h1[rd ^ 1], g_c1[rd ^ 1],
                           Wgi1, Wgh1, Wli1, Wlh1, bgi1, bgh1, bli1, blh1);
            }
        }
        if (ph < TT) grid_sync(++ep);
    }
}

// Final projection: out[i,p] = h1[i,:] @ outW[:,p] + outb[p]
__global__ void out_kernel(const float* __restrict__ outW,
                           const float* __restrict__ outb,
                           float* __restrict__ out)
{
    const int idx = blockIdx.x * blockDim.x + threadIdx.x;
    if (idx >= NN * PP) return;
    const int i = idx / PP;
    const int p = idx % PP;
    const float* h = &g_h1[0][i * HH];   // cell1(47): rd=1 -> writes h1[0]
    float acc = __ldg(&outb[p]);
#pragma unroll
    for (int mm = 0; mm < HH; ++mm)
        acc = fmaf(h[mm], __ldg(&outW[mm * PP + p]), acc);
    out[idx] = acc;
}

// ---------------- launch --------------------------------------------------------
extern "C" void kernel_launch(void* const* d_in, const int* in_sizes, int n_in,
                              void* d_out, int out_size) {
    const float* x     = (const float*)d_in[0];
    const float* adj   = (const float*)d_in[1];
    const float* gcWi0 = (const float*)d_in[2];  const float* gcbi0 = (const float*)d_in[3];
    const float* gcWh0 = (const float*)d_in[4];  const float* gcbh0 = (const float*)d_in[5];
    const float* liWi0 = (const float*)d_in[6];  const float* libi0 = (const float*)d_in[7];
    const float* liWh0 = (const float*)d_in[8];  const float* libh0 = (const float*)d_in[9];
    const float* gcWi1 = (const float*)d_in[10]; const float* gcbi1 = (const float*)d_in[11];
    const float* gcWh1 = (const float*)d_in[12]; const float* gcbh1 = (const float*)d_in[13];
    const float* liWi1 = (const float*)d_in[14]; const float* libi1 = (const float*)d_in[15];
    const float* liWh1 = (const float*)d_in[16]; const float* libh1 = (const float*)d_in[17];
    const float* outW  = (const float*)d_in[18]; const float* outb  = (const float*)d_in[19];
    float* out = (float*)d_out;

    // Preprocessing (captured in the graph; deterministic).
    // zero_kernel also resets the grid-barrier state -> graph replays are safe.
    degree_kernel<<<NN, 128>>>(adj);
    scan_kernel<<<1, 1024>>>();
    fill_kernel<<<(NN * 32 + 255) / 256, 256>>>(adj);
    xT_kernel<<<(NN * 96 + 255) / 256, 256>>>(x);
    ax_kernel<<<NN, 96>>>();
    zero_kernel<<<(NN * HH + 255) / 256, 256>>>();

    // Whole recurrence in ONE persistent kernel (48 internal grid barriers)
    persist_kernel<<<NBT, 256>>>(
        gcWi0, gcWh0, liWi0, liWh0, gcbi0, gcbh0, libi0, libh0,
        gcWi1, gcWh1, liWi1, liWh1, gcbi1, gcbh1, libi1, libh1);

    out_kernel<<<(NN * PP + 255) / 256, 256>>>(outW, outb, out);
}